// round 12
// baseline (speedup 1.0000x reference)
#include <cuda_runtime.h>
#include <cuda_bf16.h>
#include <cstdint>

#define BATCH 2
#define N1 8192
#define CIN 128

// ---------------- scratch (device globals; no allocations allowed) ----------
static __device__ float g_cv0[134217728];   // [2][8192][8192]  512 MB
static __device__ float g_cv1[33554432];    // [2][2048][8192]  128 MB
static __device__ float g_cv2[8388608];     // [2][ 512][8192]   32 MB
static __device__ float g_cv3[2097152];     // [2][ 128][8192]    8 MB
#define IDX_CROSS_STRIDE 262144            // 2*8192*16
#define IDX_PYR_BASE     1048576           // 4*262144
#define IDX_PYR1         (IDX_PYR_BASE)
#define IDX_PYR2         (IDX_PYR_BASE + 12288)
#define IDX_PYR3         (IDX_PYR_BASE + 15360)
static __device__ int   g_idx[1048576 + 16128];
static __device__ float g_costs[1048576];   // [2][64][8192]

// knn16 chunked-scan scratch, COALESCED layout: [(lvl*2+b)][slot][qi]
// slot = chunk*16 + j, up to 128 slots per query
#define SCR_LB_STRIDE 1048576              // 128*8192
#define KNN_SCR_ELEMS (8 * SCR_LB_STRIDE)  // 8.39M
static __device__ float g_scr_d[KNN_SCR_ELEMS];
static __device__ int   g_scr_i[KNN_SCR_ELEMS];

// bf16 split operands, layout [b][k][m]
#define FEAT_ELEMS 2097152                 // 2*128*8192
static __device__ __nv_bfloat16 g_f1h[FEAT_ELEMS];
static __device__ __nv_bfloat16 g_f1l[FEAT_ELEMS];
static __device__ __nv_bfloat16 g_f2h[FEAT_ELEMS];   // scaled by 1/128
static __device__ __nv_bfloat16 g_f2l[FEAT_ELEMS];

// pooled feature pyramid
#define P1_OFF 0
#define P2_OFF 524288
#define P3_OFF 655360
#define POOL_ELEMS 688128
static __device__ float         g_fpool[POOL_ELEMS];
static __device__ __nv_bfloat16 g_fph[POOL_ELEMS];   // scaled by 1/128
static __device__ __nv_bfloat16 g_fpl[POOL_ELEMS];

__device__ __forceinline__ float* cv_ptr(int lvl) {
    switch (lvl) {
        case 0: return g_cv0;
        case 1: return g_cv1;
        case 2: return g_cv2;
        default: return g_cv3;
    }
}

// ---------------- kernel 0: bf16 hi/lo split ---------------------------------
__global__ void __launch_bounds__(256) split_bf16(const float* __restrict__ feat1,
                                                  const float* __restrict__ feat2)
{
    const int i = blockIdx.x * 256 + threadIdx.x;
    if (i >= FEAT_ELEMS) return;
    {
        float a = feat1[i];
        __nv_bfloat16 h = __float2bfloat16_rn(a);
        g_f1h[i] = h;
        g_f1l[i] = __float2bfloat16_rn(a - __bfloat162float(h));
    }
    {
        float a = feat2[i] * 0.0078125f;
        __nv_bfloat16 h = __float2bfloat16_rn(a);
        g_f2h[i] = h;
        g_f2l[i] = __float2bfloat16_rn(a - __bfloat162float(h));
    }
}

// ---------------- kernel 0b: feature pooling (3-NN mean) + split -------------
__global__ void __launch_bounds__(256) pool_split(const float* __restrict__ feat2,
                                                  int src_off, int Wprev, int Nm,
                                                  int idx_off, int dst_off)
{
    const int e = blockIdx.x * 256 + threadIdx.x;
    if (e >= 2 * 128 * Nm) return;
    const int m  = e % Nm;
    const int bk = e / Nm;
    const int b  = bk >> 7;
    const float* src = (src_off < 0) ? feat2 : (g_fpool + src_off);
    const int* ip = g_idx + idx_off + ((size_t)b * Nm + m) * 3;
    const float v = (src[(size_t)bk * Wprev + ip[0]]
                   + src[(size_t)bk * Wprev + ip[1]]
                   + src[(size_t)bk * Wprev + ip[2]]) * (1.0f / 3.0f);
    g_fpool[dst_off + e] = v;
    const float s = v * 0.0078125f;
    __nv_bfloat16 h = __float2bfloat16_rn(s);
    g_fph[dst_off + e] = h;
    g_fpl[dst_off + e] = __float2bfloat16_rn(s - __bfloat162float(h));
}

// ---------------- kernel 1: cost volume GEMM (bf16 split, mma.sync) ----------
#define BK 32
#define STAGE_ELEMS 4352
#define GEMM_SMEM_BYTES (8 * STAGE_ELEMS * 2)

__device__ __forceinline__ void cp_async16(void* smem, const void* gmem) {
    unsigned saddr = (unsigned)__cvta_generic_to_shared(smem);
    asm volatile("cp.async.cg.shared.global [%0], [%1], 16;\n" :: "r"(saddr), "l"(gmem));
}
__device__ __forceinline__ void ldsm4t(uint32_t r[4], const __nv_bfloat16* p) {
    unsigned saddr = (unsigned)__cvta_generic_to_shared((void*)p);
    asm volatile("ldmatrix.sync.aligned.m8n8.x4.trans.shared.b16 {%0,%1,%2,%3}, [%4];"
                 : "=r"(r[0]), "=r"(r[1]), "=r"(r[2]), "=r"(r[3]) : "r"(saddr));
}
__device__ __forceinline__ void mma16816(float d[4], const uint32_t a[4], const uint32_t b[2]) {
    asm volatile("mma.sync.aligned.m16n8k16.row.col.f32.bf16.bf16.f32 "
                 "{%0,%1,%2,%3}, {%4,%5,%6,%7}, {%8,%9}, {%0,%1,%2,%3};"
                 : "+f"(d[0]), "+f"(d[1]), "+f"(d[2]), "+f"(d[3])
                 : "r"(a[0]), "r"(a[1]), "r"(a[2]), "r"(a[3]), "r"(b[0]), "r"(b[1]));
}

__global__ void __launch_bounds__(256) gemm_cv_mma(int lvl, int Nm, int poff)
{
    extern __shared__ __nv_bfloat16 sm[];
    __nv_bfloat16* sAh = sm;
    __nv_bfloat16* sAl = sm + 2 * STAGE_ELEMS;
    __nv_bfloat16* sBh = sm + 4 * STAGE_ELEMS;
    __nv_bfloat16* sBl = sm + 6 * STAGE_ELEMS;

    const int b  = blockIdx.z;
    const int m0 = blockIdx.y * 128;
    const int n0 = blockIdx.x * 128;
    const int tid  = threadIdx.x;
    const int lane = tid & 31;
    const int warp = tid >> 5;
    const int wm = (warp & 3) * 32;
    const int wn = (warp >> 2) * 64;

    const __nv_bfloat16* Ahp = (lvl == 0) ? g_f2h : (g_fph + poff);
    const __nv_bfloat16* Alp = (lvl == 0) ? g_f2l : (g_fpl + poff);
    const __nv_bfloat16* gAh = Ahp + (size_t)b * CIN * Nm + m0;
    const __nv_bfloat16* gAl = Alp + (size_t)b * CIN * Nm + m0;
    const __nv_bfloat16* gBh = g_f1h + (size_t)b * CIN * 8192 + n0;
    const __nv_bfloat16* gBl = g_f1l + (size_t)b * CIN * 8192 + n0;

    const int l_row0 = tid >> 4;
    const int l_col0 = (tid & 15) * 8;
#define LOAD_STAGE(stg, k0)                                                          \
    {                                                                                \
        _Pragma("unroll")                                                            \
        for (int i = 0; i < 2; i++) {                                                \
            int row = l_row0 + i * 16;                                               \
            int sofs = (stg) * STAGE_ELEMS + row * 136 + l_col0;                     \
            cp_async16(sAh + sofs, gAh + (size_t)((k0) + row) * Nm + l_col0);        \
            cp_async16(sAl + sofs, gAl + (size_t)((k0) + row) * Nm + l_col0);        \
            cp_async16(sBh + sofs, gBh + (size_t)((k0) + row) * 8192 + l_col0);      \
            cp_async16(sBl + sofs, gBl + (size_t)((k0) + row) * 8192 + l_col0);      \
        }                                                                            \
        asm volatile("cp.async.commit_group;\n" ::);                                 \
    }

    float acc[2][8][4];
#pragma unroll
    for (int mt = 0; mt < 2; mt++)
#pragma unroll
        for (int j = 0; j < 8; j++)
#pragma unroll
            for (int r = 0; r < 4; r++) acc[mt][j][r] = 0.0f;

    const int a_row = (lane & 7) + ((lane >> 4) << 3);
    const int a_col = ((lane >> 3) & 1) * 8;
    const int b_row = (lane & 7) + (((lane >> 3) & 1) << 3);
    const int b_col = ((lane >> 4) << 3);

    LOAD_STAGE(0, 0)

    const int NCHUNK = CIN / BK;
#pragma unroll
    for (int c = 0; c < NCHUNK; c++) {
        if (c + 1 < NCHUNK) {
            LOAD_STAGE((c + 1) & 1, (c + 1) * BK)
            asm volatile("cp.async.wait_group 1;\n" ::);
        } else {
            asm volatile("cp.async.wait_group 0;\n" ::);
        }
        __syncthreads();

        const int stg = (c & 1) * STAGE_ELEMS;
#pragma unroll
        for (int ks = 0; ks < 2; ks++) {
            const int kb = ks * 16;
            uint32_t ah[2][4], al[2][4];
#pragma unroll
            for (int mt = 0; mt < 2; mt++) {
                int ofs = stg + (kb + a_row) * 136 + wm + mt * 16 + a_col;
                ldsm4t(ah[mt], sAh + ofs);
                ldsm4t(al[mt], sAl + ofs);
            }
            uint32_t bh[8][2], bl[8][2];
#pragma unroll
            for (int jp = 0; jp < 4; jp++) {
                int ofs = stg + (kb + b_row) * 136 + wn + jp * 16 + b_col;
                uint32_t r[4];
                ldsm4t(r, sBh + ofs);
                bh[2 * jp][0] = r[0]; bh[2 * jp][1] = r[1];
                bh[2 * jp + 1][0] = r[2]; bh[2 * jp + 1][1] = r[3];
                ldsm4t(r, sBl + ofs);
                bl[2 * jp][0] = r[0]; bl[2 * jp][1] = r[1];
                bl[2 * jp + 1][0] = r[2]; bl[2 * jp + 1][1] = r[3];
            }
#pragma unroll
            for (int mt = 0; mt < 2; mt++)
#pragma unroll
                for (int j = 0; j < 8; j++) {
                    mma16816(acc[mt][j], ah[mt], bh[j]);
                    mma16816(acc[mt][j], ah[mt], bl[j]);
                    mma16816(acc[mt][j], al[mt], bh[j]);
                }
        }
        __syncthreads();
    }

    const int g = lane >> 2;
    const int t = lane & 3;
    float* out = cv_ptr(lvl) + (size_t)b * Nm * 8192;
#pragma unroll
    for (int mt = 0; mt < 2; mt++) {
        const int mrow = m0 + wm + mt * 16 + g;
#pragma unroll
        for (int j = 0; j < 8; j++) {
            const int n = n0 + wn + j * 8 + 2 * t;
            float2 v0 = make_float2(acc[mt][j][0], acc[mt][j][1]);
            float2 v1 = make_float2(acc[mt][j][2], acc[mt][j][3]);
            *(float2*)&out[(size_t)mrow * 8192 + n] = v0;
            *(float2*)&out[(size_t)(mrow + 8) * 8192 + n] = v1;
        }
    }
}

// ---------------- kernel 2a: chunked KNN16 scan ------------------------------
// z -> (lvl, chunk): lvl0 gets 8 chunks, lvl1 4, lvl2 2, lvl3 1 (z in [0,15)).
// float4-packed smem with precomputed norms; coalesced scratch writes.
__global__ void __launch_bounds__(128) knn16_part(const float* __restrict__ xyz1,
                                                  const float* __restrict__ x0,
                                                  const float* __restrict__ x1,
                                                  const float* __restrict__ x2,
                                                  const float* __restrict__ x3)
{
    const int z = blockIdx.z;
    int lvl, ch;
    if (z < 8)       { lvl = 0; ch = z; }
    else if (z < 12) { lvl = 1; ch = z - 8; }
    else if (z < 14) { lvl = 2; ch = z - 12; }
    else             { lvl = 3; ch = 0; }
    const float* pxyz = (lvl == 0) ? x0 : (lvl == 1) ? x1 : (lvl == 2) ? x2 : x3;
    const int Ni      = (lvl == 0) ? 8192 : (lvl == 1) ? 2048 : (lvl == 2) ? 512 : 128;
    const int nch     = (lvl == 0) ? 8 : (lvl == 1) ? 4 : (lvl == 2) ? 2 : 1;
    const int Nc      = Ni / nch;               // 1024 / 512 / 256 / 128
    const int start   = ch * Nc;

    __shared__ float4 s4[1024];
    const int b  = blockIdx.y;
    const int qi = blockIdx.x * 128 + threadIdx.x;

    const float qx = xyz1[(size_t)(b * 3 + 0) * N1 + qi];
    const float qy = xyz1[(size_t)(b * 3 + 1) * N1 + qi];
    const float qz = xyz1[(size_t)(b * 3 + 2) * N1 + qi];
    const float qq = qx * qx + qy * qy + qz * qz;

    for (int t = threadIdx.x; t < Nc; t += 128) {
        const float ix = pxyz[(size_t)(b * 3 + 0) * Ni + start + t];
        const float iy = pxyz[(size_t)(b * 3 + 1) * Ni + start + t];
        const float iz = pxyz[(size_t)(b * 3 + 2) * Ni + start + t];
        s4[t] = make_float4(ix, iy, iz, ix * ix + iy * iy + iz * iz);
    }
    __syncthreads();

    float bd[16];
    int   bi[16];
#pragma unroll
    for (int j = 0; j < 16; j++) { bd[j] = 1e30f; bi[j] = 0; }

#pragma unroll 4
    for (int t = 0; t < Nc; t++) {
        const float4 f = s4[t];
        const float d = qq + f.w - 2.0f * (qx * f.x + qy * f.y + qz * f.z);
        if (d < bd[15]) {
            bd[15] = d; bi[15] = start + t;
#pragma unroll
            for (int j = 15; j > 0; j--) {
                if (bd[j] < bd[j - 1]) {
                    float td = bd[j]; bd[j] = bd[j - 1]; bd[j - 1] = td;
                    int   ti = bi[j]; bi[j] = bi[j - 1]; bi[j - 1] = ti;
                }
            }
        }
    }

    const size_t base = (size_t)(lvl * 2 + b) * SCR_LB_STRIDE;
#pragma unroll
    for (int j = 0; j < 16; j++) {
        g_scr_d[base + (size_t)(ch * 16 + j) * 8192 + qi] = bd[j];
        g_scr_i[base + (size_t)(ch * 16 + j) * 8192 + qi] = bi[j];
    }
}

// ---------------- kernel 2b: merge chunk lists -> top-16 (coalesced reads) ---
__global__ void __launch_bounds__(256) knn16_merge()
{
    const int g = blockIdx.x * 256 + threadIdx.x;   // 0 .. 4*2*8192-1
    const int lvl = g >> 14;
    const int rem = g & 16383;
    const int b = rem >> 13;
    const int qi = rem & 8191;
    const int nslots = ((lvl == 0) ? 8 : (lvl == 1) ? 4 : (lvl == 2) ? 2 : 1) * 16;

    const size_t base = (size_t)(lvl * 2 + b) * SCR_LB_STRIDE;
    float bd[16];
    int   bi[16];
#pragma unroll
    for (int j = 0; j < 16; j++) { bd[j] = 1e30f; bi[j] = 0; }

    for (int s = 0; s < nslots; s++) {
        const float d = g_scr_d[base + (size_t)s * 8192 + qi];
        const int   ii = g_scr_i[base + (size_t)s * 8192 + qi];
        if (d < bd[15]) {
            bd[15] = d; bi[15] = ii;
#pragma unroll
            for (int k = 15; k > 0; k--) {
                if (bd[k] < bd[k - 1]) {
                    float td = bd[k]; bd[k] = bd[k - 1]; bd[k - 1] = td;
                    int   ti = bi[k]; bi[k] = bi[k - 1]; bi[k - 1] = ti;
                }
            }
        }
    }

    int* out = g_idx + (size_t)lvl * IDX_CROSS_STRIDE + ((size_t)b * N1 + qi) * 16;
#pragma unroll
    for (int j = 0; j < 16; j++) out[j] = bi[j];
}

// ---------------- kernel 2c: FUSED warp-per-query KNN3, all 3 levels ---------
__global__ void __launch_bounds__(256) knn3_all(const float* __restrict__ x0,
                                                const float* __restrict__ x1,
                                                const float* __restrict__ x2,
                                                const float* __restrict__ x3)
{
    const int l = blockIdx.z;
    const float* qxyz; const float* pxyz; int Nq, Ni, out_off;
    if (l == 0)      { qxyz = x1; pxyz = x0; Nq = 2048; Ni = 8192; out_off = IDX_PYR1; }
    else if (l == 1) { qxyz = x2; pxyz = x1; Nq = 512;  Ni = 2048; out_off = IDX_PYR2; }
    else             { qxyz = x3; pxyz = x2; Nq = 128;  Ni = 512;  out_off = IDX_PYR3; }
    if (blockIdx.x * 8 >= Nq) return;

    const int CH = 2048;
    __shared__ float sx[CH], sy[CH], sz[CH];
    const int b    = blockIdx.y;
    const int w    = threadIdx.x >> 5;
    const int lane = threadIdx.x & 31;
    const int qi   = blockIdx.x * 8 + w;

    const float qx = qxyz[(size_t)(b * 3 + 0) * Nq + qi];
    const float qy = qxyz[(size_t)(b * 3 + 1) * Nq + qi];
    const float qz = qxyz[(size_t)(b * 3 + 2) * Nq + qi];
    const float qq = qx * qx + qy * qy + qz * qz;

    float bd[3];
    int   bi[3];
#pragma unroll
    for (int j = 0; j < 3; j++) { bd[j] = 1e30f; bi[j] = -(lane + 1); }

    for (int c0 = 0; c0 < Ni; c0 += CH) {
        const int cnt = min(CH, Ni - c0);
        __syncthreads();
        for (int t = threadIdx.x; t < cnt; t += 256) {
            sx[t] = pxyz[(size_t)(b * 3 + 0) * Ni + c0 + t];
            sy[t] = pxyz[(size_t)(b * 3 + 1) * Ni + c0 + t];
            sz[t] = pxyz[(size_t)(b * 3 + 2) * Ni + c0 + t];
        }
        __syncthreads();
        for (int t = lane; t < cnt; t += 32) {
            const float ix = sx[t], iy = sy[t], iz = sz[t];
            const float ii = ix * ix + iy * iy + iz * iz;
            const float d  = qq + ii - 2.0f * (qx * ix + qy * iy + qz * iz);
            if (d < bd[2]) {
                bd[2] = d; bi[2] = c0 + t;
#pragma unroll
                for (int j = 2; j > 0; j--) {
                    if (bd[j] < bd[j - 1]) {
                        float td = bd[j]; bd[j] = bd[j - 1]; bd[j - 1] = td;
                        int   ti = bi[j]; bi[j] = bi[j - 1]; bi[j - 1] = ti;
                    }
                }
            }
        }
    }

    int   p   = 0;
    float myd = bd[0];
    int   myi = bi[0];
    int   res = 0;
#pragma unroll
    for (int j = 0; j < 3; j++) {
        float d = myd; int ii = myi;
#pragma unroll
        for (int off = 16; off; off >>= 1) {
            float od = __shfl_xor_sync(0xFFFFFFFF, d, off);
            int   oi = __shfl_xor_sync(0xFFFFFFFF, ii, off);
            if (od < d || (od == d && oi < ii)) { d = od; ii = oi; }
        }
        if (lane == j) res = ii;
        if (myi == ii) {
            p++;
            if (p < 3) { myd = bd[p]; myi = bi[p]; }
            else       { myd = 1e30f; myi = -(lane + 33); }
        }
    }
    if (lane < 3)
        g_idx[out_off + ((size_t)b * Nq + qi) * 3 + lane] = res;
}

// ---------------- kernel 4: FUSED per-level matching cost MLP ----------------
__global__ void __launch_bounds__(128) lc_all(const float* __restrict__ xyz1,
                                              const float* __restrict__ x0,
                                              const float* __restrict__ x1,
                                              const float* __restrict__ x2,
                                              const float* __restrict__ x3,
                                              const float* __restrict__ w1,
                                              const float* __restrict__ b1,
                                              const float* __restrict__ w2,
                                              const float* __restrict__ b2)
{
    __shared__ float sw1[64], sb1[16], sw2[256], sb2[16];
    const int t = threadIdx.x;
    if (t < 64) sw1[t] = w1[t];
    if (t < 16) sb1[t] = b1[t];
    for (int i = t; i < 256; i += 128) sw2[i] = w2[i];
    if (t >= 64 && t < 80) sb2[t - 64] = b2[t - 64];
    __syncthreads();

    const int lvl = blockIdx.z;
    const float* xyz2 = (lvl == 0) ? x0 : (lvl == 1) ? x1 : (lvl == 2) ? x2 : x3;
    const int Nl      = (lvl == 0) ? 8192 : (lvl == 1) ? 2048 : (lvl == 2) ? 512 : 128;

    const int b = blockIdx.y;
    const int n = blockIdx.x * 128 + t;
    const float* cvT = cv_ptr(lvl);
    const int* ip = g_idx + (size_t)lvl * IDX_CROSS_STRIDE + ((size_t)b * N1 + n) * 16;

    const float px = xyz1[(size_t)(b * 3 + 0) * N1 + n];
    const float py = xyz1[(size_t)(b * 3 + 1) * N1 + n];
    const float pz = xyz1[(size_t)(b * 3 + 2) * N1 + n];

    float acc[16];
#pragma unroll
    for (int o = 0; o < 16; o++) acc[o] = 0.0f;

#pragma unroll
    for (int half = 0; half < 2; half++) {
        // prefetch 8 neighbors' xyz + corr (32 loads in flight)
        float cx[8], cy[8], cz[8], cc[8];
#pragma unroll
        for (int k = 0; k < 8; k++) {
            const int i = ip[half * 8 + k];
            cx[k] = xyz2[(size_t)(b * 3 + 0) * Nl + i];
            cy[k] = xyz2[(size_t)(b * 3 + 1) * Nl + i];
            cz[k] = xyz2[(size_t)(b * 3 + 2) * Nl + i];
            cc[k] = cvT[((size_t)b * Nl + i) * 8192 + n];
        }
#pragma unroll
        for (int k = 0; k < 8; k++) {
            const float dx = cx[k] - px;
            const float dy = cy[k] - py;
            const float dz = cz[k] - pz;
            const float corr = cc[k];
            float h1[16];
#pragma unroll
            for (int o = 0; o < 16; o++) {
                float a = fmaf(sw1[o * 4 + 0], dx, sb1[o]);
                a = fmaf(sw1[o * 4 + 1], dy, a);
                a = fmaf(sw1[o * 4 + 2], dz, a);
                a = fmaf(sw1[o * 4 + 3], corr, a);
                h1[o] = fmaxf(a, 0.0f);
            }
#pragma unroll
            for (int o2 = 0; o2 < 16; o2++) {
                float a = sb2[o2];
#pragma unroll
                for (int o = 0; o < 16; o++) a = fmaf(sw2[o2 * 16 + o], h1[o], a);
                acc[o2] += fmaxf(a, 0.0f);
            }
        }
    }
#pragma unroll
    for (int o2 = 0; o2 < 16; o2++)
        g_costs[((size_t)b * 64 + lvl * 16 + o2) * N1 + n] = acc[o2];
}

// ---------------- kernel 5: final 64x64 MLP ---------------------------------
__global__ void __launch_bounds__(256) final_mlp(const float* __restrict__ wm,
                                                 const float* __restrict__ bm,
                                                 float* __restrict__ out)
{
    __shared__ float swm[4096];
    __shared__ float sbm[64];
    const int t = threadIdx.x;
    for (int i = t; i < 4096; i += 256) swm[i] = wm[i];
    if (t < 64) sbm[t] = bm[t];
    __syncthreads();

    const int b = blockIdx.y;
    const int n = blockIdx.x * 256 + t;

    float c[64];
#pragma unroll
    for (int cc = 0; cc < 64; cc++)
        c[cc] = g_costs[((size_t)b * 64 + cc) * N1 + n];

#pragma unroll 4
    for (int o = 0; o < 64; o++) {
        float a = sbm[o];
#pragma unroll
        for (int cc = 0; cc < 64; cc++)
            a = fmaf(swm[o * 64 + cc], c[cc], a);
        out[((size_t)b * 64 + o) * N1 + n] = fmaxf(a, 0.0f);
    }
}

// ---------------- launcher ---------------------------------------------------
extern "C" void kernel_launch(void* const* d_in, const int* in_sizes, int n_in,
                              void* d_out, int out_size)
{
    const float* xyz1   = (const float*)d_in[0];
    const float* xyz2_0 = (const float*)d_in[1];
    const float* xyz2_1 = (const float*)d_in[2];
    const float* xyz2_2 = (const float*)d_in[3];
    const float* xyz2_3 = (const float*)d_in[4];
    const float* feat1  = (const float*)d_in[5];
    const float* feat2  = (const float*)d_in[6];
    const float* w1 = (const float*)d_in[7];
    const float* b1 = (const float*)d_in[8];
    const float* w2 = (const float*)d_in[9];
    const float* b2 = (const float*)d_in[10];
    const float* wm = (const float*)d_in[11];
    const float* bm = (const float*)d_in[12];
    float* out = (float*)d_out;

    static bool init = false;
    static cudaStream_t s1, s2;
    static cudaEvent_t ev0, evSplit, evCv, evK16;
    if (!init) {
        cudaFuncSetAttribute(gemm_cv_mma, cudaFuncAttributeMaxDynamicSharedMemorySize,
                             GEMM_SMEM_BYTES);
        cudaStreamCreateWithFlags(&s1, cudaStreamNonBlocking);
        cudaStreamCreateWithFlags(&s2, cudaStreamNonBlocking);
        cudaEventCreateWithFlags(&ev0,     cudaEventDisableTiming);
        cudaEventCreateWithFlags(&evSplit, cudaEventDisableTiming);
        cudaEventCreateWithFlags(&evCv,    cudaEventDisableTiming);
        cudaEventCreateWithFlags(&evK16,   cudaEventDisableTiming);
        init = true;
    }

    // ---- fork ----
    cudaEventRecord(ev0, 0);
    cudaStreamWaitEvent(s1, ev0, 0);
    cudaStreamWaitEvent(s2, ev0, 0);

    // #1: pyramid KNN (s1)
    knn3_all<<<dim3(256, 2, 3), 256, 0, s1>>>(xyz2_0, xyz2_1, xyz2_2, xyz2_3);

    // #2: bf16 split (default); record for s1's gemms
    split_bf16<<<FEAT_ELEMS / 256, 256>>>(feat1, feat2);
    cudaEventRecord(evSplit, 0);

    // #3: cost volume GEMM level 0 (default)
    gemm_cv_mma<<<dim3(64, 64, 2), 256, GEMM_SMEM_BYTES>>>(0, 8192, 0);

    // #4: cross KNN chunked scan (s2)  <-- profiled launch
    knn16_part<<<dim3(64, 2, 15), 128, 0, s2>>>(xyz1, xyz2_0, xyz2_1, xyz2_2, xyz2_3);

    // #5-7: feature pooling cascade (s1, after knn3)
    pool_split<<<2048, 256, 0, s1>>>(feat2, -1,     8192, 2048, IDX_PYR1, P1_OFF);
    pool_split<<< 512, 256, 0, s1>>>(feat2, P1_OFF, 2048,  512, IDX_PYR2, P2_OFF);
    pool_split<<< 128, 256, 0, s1>>>(feat2, P2_OFF,  512,  128, IDX_PYR3, P3_OFF);

    // #8-10: pooled-feature GEMMs on s1 — OVERLAP with gemm0 (need split only)
    cudaStreamWaitEvent(s1, evSplit, 0);
    gemm_cv_mma<<<dim3(64, 16, 2), 256, GEMM_SMEM_BYTES, s1>>>(1, 2048, P1_OFF);
    gemm_cv_mma<<<dim3(64,  4, 2), 256, GEMM_SMEM_BYTES, s1>>>(2,  512, P2_OFF);
    gemm_cv_mma<<<dim3(64,  1, 2), 256, GEMM_SMEM_BYTES, s1>>>(3,  128, P3_OFF);
    cudaEventRecord(evCv, s1);

    // #11: merge chunk results (s2)
    knn16_merge<<<256, 256, 0, s2>>>();
    cudaEventRecord(evK16, s2);

    // join everything, then matching cost + final MLP on default stream
    cudaStreamWaitEvent(0, evCv, 0);
    cudaStreamWaitEvent(0, evK16, 0);
    lc_all<<<dim3(64, 2, 4), 128>>>(xyz1, xyz2_0, xyz2_1, xyz2_2, xyz2_3,
                                    w1, b1, w2, b2);
    final_mlp<<<dim3(32, 2), 256>>>(wm, bm, out);
}

// round 14
// speedup vs baseline: 1.1784x; 1.1784x over previous
#include <cuda_runtime.h>
#include <cuda_bf16.h>
#include <cstdint>

#define BATCH 2
#define N1 8192
#define CIN 128

// ---------------- scratch (device globals; no allocations allowed) ----------
static __device__ float g_cv0[134217728];   // [2][8192][8192]  512 MB
static __device__ float g_cv1[33554432];    // [2][2048][8192]  128 MB
static __device__ float g_cv2[8388608];     // [2][ 512][8192]   32 MB
static __device__ float g_cv3[2097152];     // [2][ 128][8192]    8 MB
#define IDX_CROSS_STRIDE 262144            // 2*8192*16
#define IDX_PYR_BASE     1048576
#define IDX_PYR1         (IDX_PYR_BASE)
#define IDX_PYR2         (IDX_PYR_BASE + 12288)
#define IDX_PYR3         (IDX_PYR_BASE + 15360)
static __device__ int   g_idx[1048576 + 16128];
static __device__ float g_costs[1048576];   // [2][64][8192]

// bf16 split operands, layout [b][k][m]
#define FEAT_ELEMS 2097152                 // 2*128*8192
static __device__ __nv_bfloat16 g_f1h[FEAT_ELEMS];
static __device__ __nv_bfloat16 g_f1l[FEAT_ELEMS];
static __device__ __nv_bfloat16 g_f2h[FEAT_ELEMS];   // scaled by 1/128
static __device__ __nv_bfloat16 g_f2l[FEAT_ELEMS];

// pooled feature pyramid
#define P1_OFF 0
#define P2_OFF 524288
#define P3_OFF 655360
#define POOL_ELEMS 688128
static __device__ float         g_fpool[POOL_ELEMS];
static __device__ __nv_bfloat16 g_fph[POOL_ELEMS];   // scaled by 1/128
static __device__ __nv_bfloat16 g_fpl[POOL_ELEMS];

__device__ __forceinline__ float* cv_ptr(int lvl) {
    switch (lvl) {
        case 0: return g_cv0;
        case 1: return g_cv1;
        case 2: return g_cv2;
        default: return g_cv3;
    }
}

// ---------------- kernel 0: bf16 hi/lo split ---------------------------------
__global__ void __launch_bounds__(256) split_bf16(const float* __restrict__ feat1,
                                                  const float* __restrict__ feat2)
{
    const int i = blockIdx.x * 256 + threadIdx.x;
    if (i >= FEAT_ELEMS) return;
    {
        float a = feat1[i];
        __nv_bfloat16 h = __float2bfloat16_rn(a);
        g_f1h[i] = h;
        g_f1l[i] = __float2bfloat16_rn(a - __bfloat162float(h));
    }
    {
        float a = feat2[i] * 0.0078125f;
        __nv_bfloat16 h = __float2bfloat16_rn(a);
        g_f2h[i] = h;
        g_f2l[i] = __float2bfloat16_rn(a - __bfloat162float(h));
    }
}

// ---------------- kernel 0b: feature pooling (3-NN mean) + split -------------
__global__ void __launch_bounds__(256) pool_split(const float* __restrict__ feat2,
                                                  int src_off, int Wprev, int Nm,
                                                  int idx_off, int dst_off)
{
    const int e = blockIdx.x * 256 + threadIdx.x;
    if (e >= 2 * 128 * Nm) return;
    const int m  = e % Nm;
    const int bk = e / Nm;
    const int b  = bk >> 7;
    const float* src = (src_off < 0) ? feat2 : (g_fpool + src_off);
    const int* ip = g_idx + idx_off + ((size_t)b * Nm + m) * 3;
    const float v = (src[(size_t)bk * Wprev + ip[0]]
                   + src[(size_t)bk * Wprev + ip[1]]
                   + src[(size_t)bk * Wprev + ip[2]]) * (1.0f / 3.0f);
    g_fpool[dst_off + e] = v;
    const float s = v * 0.0078125f;
    __nv_bfloat16 h = __float2bfloat16_rn(s);
    g_fph[dst_off + e] = h;
    g_fpl[dst_off + e] = __float2bfloat16_rn(s - __bfloat162float(h));
}

// ---------------- kernel 1: cost volume GEMM (bf16 split, mma.sync) ----------
#define BK 32
#define STAGE_ELEMS 4352
#define GEMM_SMEM_BYTES (8 * STAGE_ELEMS * 2)

__device__ __forceinline__ void cp_async16(void* smem, const void* gmem) {
    unsigned saddr = (unsigned)__cvta_generic_to_shared(smem);
    asm volatile("cp.async.cg.shared.global [%0], [%1], 16;\n" :: "r"(saddr), "l"(gmem));
}
__device__ __forceinline__ void ldsm4t(uint32_t r[4], const __nv_bfloat16* p) {
    unsigned saddr = (unsigned)__cvta_generic_to_shared((void*)p);
    asm volatile("ldmatrix.sync.aligned.m8n8.x4.trans.shared.b16 {%0,%1,%2,%3}, [%4];"
                 : "=r"(r[0]), "=r"(r[1]), "=r"(r[2]), "=r"(r[3]) : "r"(saddr));
}
__device__ __forceinline__ void mma16816(float d[4], const uint32_t a[4], const uint32_t b[2]) {
    asm volatile("mma.sync.aligned.m16n8k16.row.col.f32.bf16.bf16.f32 "
                 "{%0,%1,%2,%3}, {%4,%5,%6,%7}, {%8,%9}, {%0,%1,%2,%3};"
                 : "+f"(d[0]), "+f"(d[1]), "+f"(d[2]), "+f"(d[3])
                 : "r"(a[0]), "r"(a[1]), "r"(a[2]), "r"(a[3]), "r"(b[0]), "r"(b[1]));
}

__global__ void __launch_bounds__(256) gemm_cv_mma(int lvl, int Nm, int poff)
{
    extern __shared__ __nv_bfloat16 sm[];
    __nv_bfloat16* sAh = sm;
    __nv_bfloat16* sAl = sm + 2 * STAGE_ELEMS;
    __nv_bfloat16* sBh = sm + 4 * STAGE_ELEMS;
    __nv_bfloat16* sBl = sm + 6 * STAGE_ELEMS;

    const int b  = blockIdx.z;
    const int m0 = blockIdx.y * 128;
    const int n0 = blockIdx.x * 128;
    const int tid  = threadIdx.x;
    const int lane = tid & 31;
    const int warp = tid >> 5;
    const int wm = (warp & 3) * 32;
    const int wn = (warp >> 2) * 64;

    const __nv_bfloat16* Ahp = (lvl == 0) ? g_f2h : (g_fph + poff);
    const __nv_bfloat16* Alp = (lvl == 0) ? g_f2l : (g_fpl + poff);
    const __nv_bfloat16* gAh = Ahp + (size_t)b * CIN * Nm + m0;
    const __nv_bfloat16* gAl = Alp + (size_t)b * CIN * Nm + m0;
    const __nv_bfloat16* gBh = g_f1h + (size_t)b * CIN * 8192 + n0;
    const __nv_bfloat16* gBl = g_f1l + (size_t)b * CIN * 8192 + n0;

    const int l_row0 = tid >> 4;
    const int l_col0 = (tid & 15) * 8;
#define LOAD_STAGE(stg, k0)                                                          \
    {                                                                                \
        _Pragma("unroll")                                                            \
        for (int i = 0; i < 2; i++) {                                                \
            int row = l_row0 + i * 16;                                               \
            int sofs = (stg) * STAGE_ELEMS + row * 136 + l_col0;                     \
            cp_async16(sAh + sofs, gAh + (size_t)((k0) + row) * Nm + l_col0);        \
            cp_async16(sAl + sofs, gAl + (size_t)((k0) + row) * Nm + l_col0);        \
            cp_async16(sBh + sofs, gBh + (size_t)((k0) + row) * 8192 + l_col0);      \
            cp_async16(sBl + sofs, gBl + (size_t)((k0) + row) * 8192 + l_col0);      \
        }                                                                            \
        asm volatile("cp.async.commit_group;\n" ::);                                 \
    }

    float acc[2][8][4];
#pragma unroll
    for (int mt = 0; mt < 2; mt++)
#pragma unroll
        for (int j = 0; j < 8; j++)
#pragma unroll
            for (int r = 0; r < 4; r++) acc[mt][j][r] = 0.0f;

    const int a_row = (lane & 7) + ((lane >> 4) << 3);
    const int a_col = ((lane >> 3) & 1) * 8;
    const int b_row = (lane & 7) + (((lane >> 3) & 1) << 3);
    const int b_col = ((lane >> 4) << 3);

    LOAD_STAGE(0, 0)

    const int NCHUNK = CIN / BK;
#pragma unroll
    for (int c = 0; c < NCHUNK; c++) {
        if (c + 1 < NCHUNK) {
            LOAD_STAGE((c + 1) & 1, (c + 1) * BK)
            asm volatile("cp.async.wait_group 1;\n" ::);
        } else {
            asm volatile("cp.async.wait_group 0;\n" ::);
        }
        __syncthreads();

        const int stg = (c & 1) * STAGE_ELEMS;
#pragma unroll
        for (int ks = 0; ks < 2; ks++) {
            const int kb = ks * 16;
            uint32_t ah[2][4], al[2][4];
#pragma unroll
            for (int mt = 0; mt < 2; mt++) {
                int ofs = stg + (kb + a_row) * 136 + wm + mt * 16 + a_col;
                ldsm4t(ah[mt], sAh + ofs);
                ldsm4t(al[mt], sAl + ofs);
            }
            uint32_t bh[8][2], bl[8][2];
#pragma unroll
            for (int jp = 0; jp < 4; jp++) {
                int ofs = stg + (kb + b_row) * 136 + wn + jp * 16 + b_col;
                uint32_t r[4];
                ldsm4t(r, sBh + ofs);
                bh[2 * jp][0] = r[0]; bh[2 * jp][1] = r[1];
                bh[2 * jp + 1][0] = r[2]; bh[2 * jp + 1][1] = r[3];
                ldsm4t(r, sBl + ofs);
                bl[2 * jp][0] = r[0]; bl[2 * jp][1] = r[1];
                bl[2 * jp + 1][0] = r[2]; bl[2 * jp + 1][1] = r[3];
            }
#pragma unroll
            for (int mt = 0; mt < 2; mt++)
#pragma unroll
                for (int j = 0; j < 8; j++) {
                    mma16816(acc[mt][j], ah[mt], bh[j]);
                    mma16816(acc[mt][j], ah[mt], bl[j]);
                    mma16816(acc[mt][j], al[mt], bh[j]);
                }
        }
        __syncthreads();
    }

    const int g = lane >> 2;
    const int t = lane & 3;
    float* out = cv_ptr(lvl) + (size_t)b * Nm * 8192;
#pragma unroll
    for (int mt = 0; mt < 2; mt++) {
        const int mrow = m0 + wm + mt * 16 + g;
#pragma unroll
        for (int j = 0; j < 8; j++) {
            const int n = n0 + wn + j * 8 + 2 * t;
            float2 v0 = make_float2(acc[mt][j][0], acc[mt][j][1]);
            float2 v1 = make_float2(acc[mt][j][2], acc[mt][j][3]);
            *(float2*)&out[(size_t)mrow * 8192 + n] = v0;
            *(float2*)&out[(size_t)(mrow + 8) * 8192 + n] = v1;
        }
    }
}

// ---------------- kernel 2a: ballot-filtered warp-cooperative KNN16 ----------
// One warp per (query, batch, level). Sorted top-16 lives distributed across
// lanes 0-15 (lane j = j-th best, ascending). Per step, 32 candidates are
// evaluated in parallel; a ballot against the 16th-best threshold gates a
// serialized distributed insert (~14 warp-instr, ~110 events per query).
// Candidates processed in ascending index; position count(v <= d) + strict
// threshold preserve the serial scan's tie behavior exactly.
__global__ void __launch_bounds__(256) knn16_ballot(const float* __restrict__ xyz1,
                                                    const float* __restrict__ x0,
                                                    const float* __restrict__ x1,
                                                    const float* __restrict__ x2,
                                                    const float* __restrict__ x3)
{
    const int lvl = blockIdx.z;
    const float* pxyz = (lvl == 0) ? x0 : (lvl == 1) ? x1 : (lvl == 2) ? x2 : x3;
    const int Ni      = (lvl == 0) ? 8192 : (lvl == 1) ? 2048 : (lvl == 2) ? 512 : 128;

    __shared__ float4 s4[2048];                 // 32 KB staging
    const int b    = blockIdx.y;
    const int warp = threadIdx.x >> 5;
    const int lane = threadIdx.x & 31;
    const int qi   = blockIdx.x * 8 + warp;

    const float qx = xyz1[(size_t)(b * 3 + 0) * N1 + qi];
    const float qy = xyz1[(size_t)(b * 3 + 1) * N1 + qi];
    const float qz = xyz1[(size_t)(b * 3 + 2) * N1 + qi];
    const float qq = qx * qx + qy * qy + qz * qz;

    float myv = 1e30f;                          // lane j (<16): j-th best dist
    int   myi = 0;
    float thr = 1e30f;                          // current 16th-best (uniform)

    for (int c0 = 0; c0 < Ni; c0 += 2048) {
        const int cnt = min(2048, Ni - c0);     // always a multiple of 32
        __syncthreads();
        for (int t = threadIdx.x; t < cnt; t += 256) {
            const float ix = pxyz[(size_t)(b * 3 + 0) * Ni + c0 + t];
            const float iy = pxyz[(size_t)(b * 3 + 1) * Ni + c0 + t];
            const float iz = pxyz[(size_t)(b * 3 + 2) * Ni + c0 + t];
            s4[t] = make_float4(ix, iy, iz, ix * ix + iy * iy + iz * iz);
        }
        __syncthreads();

        for (int t = 0; t < cnt; t += 32) {
            const float4 f = s4[t + lane];
            const float d = qq + f.w - 2.0f * (qx * f.x + qy * f.y + qz * f.z);
            unsigned q = __ballot_sync(0xFFFFFFFF, d < thr);
            while (q) {
                const int src = __ffs(q) - 1;
                q &= q - 1;
                const float dd = __shfl_sync(0xFFFFFFFF, d, src);
                if (dd < thr) {                 // uniform recheck vs updated thr
                    const int ii = c0 + t + src;
                    const unsigned m =
                        __ballot_sync(0xFFFFFFFF, (lane < 16) && (myv <= dd));
                    const int p = __popc(m);    // insert position (<= 15)
                    const float vprev = __shfl_up_sync(0xFFFFFFFF, myv, 1);
                    const int   iprev = __shfl_up_sync(0xFFFFFFFF, myi, 1);
                    if (lane == p)                    { myv = dd;    myi = ii; }
                    else if (lane > p && lane < 16)   { myv = vprev; myi = iprev; }
                    thr = __shfl_sync(0xFFFFFFFF, myv, 15);
                }
            }
        }
    }

    if (lane < 16)
        g_idx[(size_t)lvl * IDX_CROSS_STRIDE + ((size_t)b * N1 + qi) * 16 + lane] = myi;
}

// ---------------- kernel 2c: FUSED warp-per-query KNN3, all 3 levels ---------
__global__ void __launch_bounds__(256) knn3_all(const float* __restrict__ x0,
                                                const float* __restrict__ x1,
                                                const float* __restrict__ x2,
                                                const float* __restrict__ x3)
{
    const int l = blockIdx.z;
    const float* qxyz; const float* pxyz; int Nq, Ni, out_off;
    if (l == 0)      { qxyz = x1; pxyz = x0; Nq = 2048; Ni = 8192; out_off = IDX_PYR1; }
    else if (l == 1) { qxyz = x2; pxyz = x1; Nq = 512;  Ni = 2048; out_off = IDX_PYR2; }
    else             { qxyz = x3; pxyz = x2; Nq = 128;  Ni = 512;  out_off = IDX_PYR3; }
    if (blockIdx.x * 8 >= Nq) return;

    const int CH = 2048;
    __shared__ float sx[CH], sy[CH], sz[CH];
    const int b    = blockIdx.y;
    const int w    = threadIdx.x >> 5;
    const int lane = threadIdx.x & 31;
    const int qi   = blockIdx.x * 8 + w;

    const float qx = qxyz[(size_t)(b * 3 + 0) * Nq + qi];
    const float qy = qxyz[(size_t)(b * 3 + 1) * Nq + qi];
    const float qz = qxyz[(size_t)(b * 3 + 2) * Nq + qi];
    const float qq = qx * qx + qy * qy + qz * qz;

    float bd[3];
    int   bi[3];
#pragma unroll
    for (int j = 0; j < 3; j++) { bd[j] = 1e30f; bi[j] = -(lane + 1); }

    for (int c0 = 0; c0 < Ni; c0 += CH) {
        const int cnt = min(CH, Ni - c0);
        __syncthreads();
        for (int t = threadIdx.x; t < cnt; t += 256) {
            sx[t] = pxyz[(size_t)(b * 3 + 0) * Ni + c0 + t];
            sy[t] = pxyz[(size_t)(b * 3 + 1) * Ni + c0 + t];
            sz[t] = pxyz[(size_t)(b * 3 + 2) * Ni + c0 + t];
        }
        __syncthreads();
        for (int t = lane; t < cnt; t += 32) {
            const float ix = sx[t], iy = sy[t], iz = sz[t];
            const float ii = ix * ix + iy * iy + iz * iz;
            const float d  = qq + ii - 2.0f * (qx * ix + qy * iy + qz * iz);
            if (d < bd[2]) {
                bd[2] = d; bi[2] = c0 + t;
#pragma unroll
                for (int j = 2; j > 0; j--) {
                    if (bd[j] < bd[j - 1]) {
                        float td = bd[j]; bd[j] = bd[j - 1]; bd[j - 1] = td;
                        int   ti = bi[j]; bi[j] = bi[j - 1]; bi[j - 1] = ti;
                    }
                }
            }
        }
    }

    int   p   = 0;
    float myd = bd[0];
    int   myi = bi[0];
    int   res = 0;
#pragma unroll
    for (int j = 0; j < 3; j++) {
        float d = myd; int ii = myi;
#pragma unroll
        for (int off = 16; off; off >>= 1) {
            float od = __shfl_xor_sync(0xFFFFFFFF, d, off);
            int   oi = __shfl_xor_sync(0xFFFFFFFF, ii, off);
            if (od < d || (od == d && oi < ii)) { d = od; ii = oi; }
        }
        if (lane == j) res = ii;
        if (myi == ii) {
            p++;
            if (p < 3) { myd = bd[p]; myi = bi[p]; }
            else       { myd = 1e30f; myi = -(lane + 33); }
        }
    }
    if (lane < 3)
        g_idx[out_off + ((size_t)b * Nq + qi) * 3 + lane] = res;
}

// ---------------- kernel 4: FUSED per-level matching cost MLP ----------------
__global__ void __launch_bounds__(128) lc_all(const float* __restrict__ xyz1,
                                              const float* __restrict__ x0,
                                              const float* __restrict__ x1,
                                              const float* __restrict__ x2,
                                              const float* __restrict__ x3,
                                              const float* __restrict__ w1,
                                              const float* __restrict__ b1,
                                              const float* __restrict__ w2,
                                              const float* __restrict__ b2)
{
    __shared__ float sw1[64], sb1[16], sw2[256], sb2[16];
    const int t = threadIdx.x;
    if (t < 64) sw1[t] = w1[t];
    if (t < 16) sb1[t] = b1[t];
    for (int i = t; i < 256; i += 128) sw2[i] = w2[i];
    if (t >= 64 && t < 80) sb2[t - 64] = b2[t - 64];
    __syncthreads();

    const int lvl = blockIdx.z;
    const float* xyz2 = (lvl == 0) ? x0 : (lvl == 1) ? x1 : (lvl == 2) ? x2 : x3;
    const int Nl      = (lvl == 0) ? 8192 : (lvl == 1) ? 2048 : (lvl == 2) ? 512 : 128;

    const int b = blockIdx.y;
    const int n = blockIdx.x * 128 + t;
    const float* cvT = cv_ptr(lvl);
    const int* ip = g_idx + (size_t)lvl * IDX_CROSS_STRIDE + ((size_t)b * N1 + n) * 16;

    const float px = xyz1[(size_t)(b * 3 + 0) * N1 + n];
    const float py = xyz1[(size_t)(b * 3 + 1) * N1 + n];
    const float pz = xyz1[(size_t)(b * 3 + 2) * N1 + n];

    float acc[16];
#pragma unroll
    for (int o = 0; o < 16; o++) acc[o] = 0.0f;

#pragma unroll
    for (int half = 0; half < 2; half++) {
        float cx[8], cy[8], cz[8], cc[8];
#pragma unroll
        for (int k = 0; k < 8; k++) {
            const int i = ip[half * 8 + k];
            cx[k] = xyz2[(size_t)(b * 3 + 0) * Nl + i];
            cy[k] = xyz2[(size_t)(b * 3 + 1) * Nl + i];
            cz[k] = xyz2[(size_t)(b * 3 + 2) * Nl + i];
            cc[k] = cvT[((size_t)b * Nl + i) * 8192 + n];
        }
#pragma unroll
        for (int k = 0; k < 8; k++) {
            const float dx = cx[k] - px;
            const float dy = cy[k] - py;
            const float dz = cz[k] - pz;
            const float corr = cc[k];
            float h1[16];
#pragma unroll
            for (int o = 0; o < 16; o++) {
                float a = fmaf(sw1[o * 4 + 0], dx, sb1[o]);
                a = fmaf(sw1[o * 4 + 1], dy, a);
                a = fmaf(sw1[o * 4 + 2], dz, a);
                a = fmaf(sw1[o * 4 + 3], corr, a);
                h1[o] = fmaxf(a, 0.0f);
            }
#pragma unroll
            for (int o2 = 0; o2 < 16; o2++) {
                float a = sb2[o2];
#pragma unroll
                for (int o = 0; o < 16; o++) a = fmaf(sw2[o2 * 16 + o], h1[o], a);
                acc[o2] += fmaxf(a, 0.0f);
            }
        }
    }
#pragma unroll
    for (int o2 = 0; o2 < 16; o2++)
        g_costs[((size_t)b * 64 + lvl * 16 + o2) * N1 + n] = acc[o2];
}

// ---------------- kernel 5: final 64x64 MLP ---------------------------------
__global__ void __launch_bounds__(256) final_mlp(const float* __restrict__ wm,
                                                 const float* __restrict__ bm,
                                                 float* __restrict__ out)
{
    __shared__ float swm[4096];
    __shared__ float sbm[64];
    const int t = threadIdx.x;
    for (int i = t; i < 4096; i += 256) swm[i] = wm[i];
    if (t < 64) sbm[t] = bm[t];
    __syncthreads();

    const int b = blockIdx.y;
    const int n = blockIdx.x * 256 + t;

    float c[64];
#pragma unroll
    for (int cc = 0; cc < 64; cc++)
        c[cc] = g_costs[((size_t)b * 64 + cc) * N1 + n];

#pragma unroll 4
    for (int o = 0; o < 64; o++) {
        float a = sbm[o];
#pragma unroll
        for (int cc = 0; cc < 64; cc++)
            a = fmaf(swm[o * 64 + cc], c[cc], a);
        out[((size_t)b * 64 + o) * N1 + n] = fmaxf(a, 0.0f);
    }
}

// ---------------- launcher ---------------------------------------------------
extern "C" void kernel_launch(void* const* d_in, const int* in_sizes, int n_in,
                              void* d_out, int out_size)
{
    const float* xyz1   = (const float*)d_in[0];
    const float* xyz2_0 = (const float*)d_in[1];
    const float* xyz2_1 = (const float*)d_in[2];
    const float* xyz2_2 = (const float*)d_in[3];
    const float* xyz2_3 = (const float*)d_in[4];
    const float* feat1  = (const float*)d_in[5];
    const float* feat2  = (const float*)d_in[6];
    const float* w1 = (const float*)d_in[7];
    const float* b1 = (const float*)d_in[8];
    const float* w2 = (const float*)d_in[9];
    const float* b2 = (const float*)d_in[10];
    const float* wm = (const float*)d_in[11];
    const float* bm = (const float*)d_in[12];
    float* out = (float*)d_out;

    static bool init = false;
    static cudaStream_t s1, s2;
    static cudaEvent_t ev0, evSplit, evCv, evK16;
    if (!init) {
        cudaFuncSetAttribute(gemm_cv_mma, cudaFuncAttributeMaxDynamicSharedMemorySize,
                             GEMM_SMEM_BYTES);
        cudaStreamCreateWithFlags(&s1, cudaStreamNonBlocking);
        cudaStreamCreateWithFlags(&s2, cudaStreamNonBlocking);
        cudaEventCreateWithFlags(&ev0,     cudaEventDisableTiming);
        cudaEventCreateWithFlags(&evSplit, cudaEventDisableTiming);
        cudaEventCreateWithFlags(&evCv,    cudaEventDisableTiming);
        cudaEventCreateWithFlags(&evK16,   cudaEventDisableTiming);
        init = true;
    }

    // ---- fork ----
    cudaEventRecord(ev0, 0);
    cudaStreamWaitEvent(s1, ev0, 0);
    cudaStreamWaitEvent(s2, ev0, 0);

    // #1: pyramid KNN (s1)
    knn3_all<<<dim3(256, 2, 3), 256, 0, s1>>>(xyz2_0, xyz2_1, xyz2_2, xyz2_3);

    // #2: bf16 split (default)
    split_bf16<<<FEAT_ELEMS / 256, 256>>>(feat1, feat2);
    cudaEventRecord(evSplit, 0);

    // #3: cost volume GEMM level 0 (default)
    gemm_cv_mma<<<dim3(64, 64, 2), 256, GEMM_SMEM_BYTES>>>(0, 8192, 0);

    // #4: cross KNN, ballot-filtered warp-cooperative (s2)  <-- profiled launch
    knn16_ballot<<<dim3(1024, 2, 4), 256, 0, s2>>>(xyz1, xyz2_0, xyz2_1, xyz2_2, xyz2_3);
    cudaEventRecord(evK16, s2);

    // #5-7: feature pooling cascade (s1, after knn3)
    pool_split<<<2048, 256, 0, s1>>>(feat2, -1,     8192, 2048, IDX_PYR1, P1_OFF);
    pool_split<<< 512, 256, 0, s1>>>(feat2, P1_OFF, 2048,  512, IDX_PYR2, P2_OFF);
    pool_split<<< 128, 256, 0, s1>>>(feat2, P2_OFF,  512,  128, IDX_PYR3, P3_OFF);

    // #8-10: pooled-feature GEMMs on s1 — overlap with gemm0
    cudaStreamWaitEvent(s1, evSplit, 0);
    gemm_cv_mma<<<dim3(64, 16, 2), 256, GEMM_SMEM_BYTES, s1>>>(1, 2048, P1_OFF);
    gemm_cv_mma<<<dim3(64,  4, 2), 256, GEMM_SMEM_BYTES, s1>>>(2,  512, P2_OFF);
    gemm_cv_mma<<<dim3(64,  1, 2), 256, GEMM_SMEM_BYTES, s1>>>(3,  128, P3_OFF);
    cudaEventRecord(evCv, s1);

    // join everything, then matching cost + final MLP on default stream
    cudaStreamWaitEvent(0, evCv, 0);
    cudaStreamWaitEvent(0, evK16, 0);
    lc_all<<<dim3(64, 2, 4), 128>>>(xyz1, xyz2_0, xyz2_1, xyz2_2, xyz2_3,
                                    w1, b1, w2, b2);
    final_mlp<<<dim3(32, 2), 256>>>(wm, bm, out);
}

// round 15
// speedup vs baseline: 1.9572x; 1.6609x over previous
#include <cuda_runtime.h>
#include <cuda_bf16.h>
#include <cstdint>

#define BATCH 2
#define N1 8192
#define CIN 128

// ---------------- scratch (device globals; no allocations allowed) ----------
static __device__ float g_cv0[134217728];   // [2][8192][8192]  512 MB
static __device__ float g_cv1[33554432];    // [2][2048][8192]  128 MB
static __device__ float g_cv2[8388608];     // [2][ 512][8192]   32 MB
static __device__ float g_cv3[2097152];     // [2][ 128][8192]    8 MB
#define IDX_CROSS_STRIDE 262144            // 2*8192*16
#define IDX_PYR_BASE     1048576
#define IDX_PYR1         (IDX_PYR_BASE)
#define IDX_PYR2         (IDX_PYR_BASE + 12288)
#define IDX_PYR3         (IDX_PYR_BASE + 15360)
static __device__ int   g_idx[1048576 + 16128];
static __device__ float g_costs[1048576];   // [2][64][8192]

// bf16 split operands, layout [b][k][m]
#define FEAT_ELEMS 2097152                 // 2*128*8192
static __device__ __nv_bfloat16 g_f1h[FEAT_ELEMS];
static __device__ __nv_bfloat16 g_f1l[FEAT_ELEMS];
static __device__ __nv_bfloat16 g_f2h[FEAT_ELEMS];   // scaled by 1/128
static __device__ __nv_bfloat16 g_f2l[FEAT_ELEMS];

__device__ __forceinline__ float* cv_ptr(int lvl) {
    switch (lvl) {
        case 0: return g_cv0;
        case 1: return g_cv1;
        case 2: return g_cv2;
        default: return g_cv3;
    }
}

// ---------------- kernel 0: bf16 hi/lo split ---------------------------------
__global__ void __launch_bounds__(256) split_bf16(const float* __restrict__ feat1,
                                                  const float* __restrict__ feat2)
{
    const int i = blockIdx.x * 256 + threadIdx.x;
    if (i >= FEAT_ELEMS) return;
    {
        float a = feat1[i];
        __nv_bfloat16 h = __float2bfloat16_rn(a);
        g_f1h[i] = h;
        g_f1l[i] = __float2bfloat16_rn(a - __bfloat162float(h));
    }
    {
        float a = feat2[i] * 0.0078125f;   // fold 1/128 (exact pow2)
        __nv_bfloat16 h = __float2bfloat16_rn(a);
        g_f2h[i] = h;
        g_f2l[i] = __float2bfloat16_rn(a - __bfloat162float(h));
    }
}

// ---------------- kernel 1: cost volume GEMM (bf16 split, mma.sync) ----------
#define BK 32
#define STAGE_ELEMS 4352
#define GEMM_SMEM_BYTES (8 * STAGE_ELEMS * 2)

__device__ __forceinline__ void cp_async16(void* smem, const void* gmem) {
    unsigned saddr = (unsigned)__cvta_generic_to_shared(smem);
    asm volatile("cp.async.cg.shared.global [%0], [%1], 16;\n" :: "r"(saddr), "l"(gmem));
}
__device__ __forceinline__ void ldsm4t(uint32_t r[4], const __nv_bfloat16* p) {
    unsigned saddr = (unsigned)__cvta_generic_to_shared((void*)p);
    asm volatile("ldmatrix.sync.aligned.m8n8.x4.trans.shared.b16 {%0,%1,%2,%3}, [%4];"
                 : "=r"(r[0]), "=r"(r[1]), "=r"(r[2]), "=r"(r[3]) : "r"(saddr));
}
__device__ __forceinline__ void mma16816(float d[4], const uint32_t a[4], const uint32_t b[2]) {
    asm volatile("mma.sync.aligned.m16n8k16.row.col.f32.bf16.bf16.f32 "
                 "{%0,%1,%2,%3}, {%4,%5,%6,%7}, {%8,%9}, {%0,%1,%2,%3};"
                 : "+f"(d[0]), "+f"(d[1]), "+f"(d[2]), "+f"(d[3])
                 : "r"(a[0]), "r"(a[1]), "r"(a[2]), "r"(a[3]), "r"(b[0]), "r"(b[1]));
}

__global__ void __launch_bounds__(256) gemm_cv_mma()
{
    extern __shared__ __nv_bfloat16 sm[];
    __nv_bfloat16* sAh = sm;
    __nv_bfloat16* sAl = sm + 2 * STAGE_ELEMS;
    __nv_bfloat16* sBh = sm + 4 * STAGE_ELEMS;
    __nv_bfloat16* sBl = sm + 6 * STAGE_ELEMS;

    const int b  = blockIdx.z;
    const int m0 = blockIdx.y * 128;
    const int n0 = blockIdx.x * 128;
    const int tid  = threadIdx.x;
    const int lane = tid & 31;
    const int warp = tid >> 5;
    const int wm = (warp & 3) * 32;
    const int wn = (warp >> 2) * 64;

    const __nv_bfloat16* gAh = g_f2h + (size_t)b * CIN * 8192 + m0;
    const __nv_bfloat16* gAl = g_f2l + (size_t)b * CIN * 8192 + m0;
    const __nv_bfloat16* gBh = g_f1h + (size_t)b * CIN * 8192 + n0;
    const __nv_bfloat16* gBl = g_f1l + (size_t)b * CIN * 8192 + n0;

    const int l_row0 = tid >> 4;
    const int l_col0 = (tid & 15) * 8;
#define LOAD_STAGE(stg, k0)                                                          \
    {                                                                                \
        _Pragma("unroll")                                                            \
        for (int i = 0; i < 2; i++) {                                                \
            int row = l_row0 + i * 16;                                               \
            size_t gofs = (size_t)((k0) + row) * 8192 + l_col0;                      \
            int sofs = (stg) * STAGE_ELEMS + row * 136 + l_col0;                     \
            cp_async16(sAh + sofs, gAh + gofs);                                      \
            cp_async16(sAl + sofs, gAl + gofs);                                      \
            cp_async16(sBh + sofs, gBh + gofs);                                      \
            cp_async16(sBl + sofs, gBl + gofs);                                      \
        }                                                                            \
        asm volatile("cp.async.commit_group;\n" ::);                                 \
    }

    float acc[2][8][4];
#pragma unroll
    for (int mt = 0; mt < 2; mt++)
#pragma unroll
        for (int j = 0; j < 8; j++)
#pragma unroll
            for (int r = 0; r < 4; r++) acc[mt][j][r] = 0.0f;

    const int a_row = (lane & 7) + ((lane >> 4) << 3);
    const int a_col = ((lane >> 3) & 1) * 8;
    const int b_row = (lane & 7) + (((lane >> 3) & 1) << 3);
    const int b_col = ((lane >> 4) << 3);

    LOAD_STAGE(0, 0)

    const int NCHUNK = CIN / BK;
#pragma unroll
    for (int c = 0; c < NCHUNK; c++) {
        if (c + 1 < NCHUNK) {
            LOAD_STAGE((c + 1) & 1, (c + 1) * BK)
            asm volatile("cp.async.wait_group 1;\n" ::);
        } else {
            asm volatile("cp.async.wait_group 0;\n" ::);
        }
        __syncthreads();

        const int stg = (c & 1) * STAGE_ELEMS;
#pragma unroll
        for (int ks = 0; ks < 2; ks++) {
            const int kb = ks * 16;
            uint32_t ah[2][4], al[2][4];
#pragma unroll
            for (int mt = 0; mt < 2; mt++) {
                int ofs = stg + (kb + a_row) * 136 + wm + mt * 16 + a_col;
                ldsm4t(ah[mt], sAh + ofs);
                ldsm4t(al[mt], sAl + ofs);
            }
            uint32_t bh[8][2], bl[8][2];
#pragma unroll
            for (int jp = 0; jp < 4; jp++) {
                int ofs = stg + (kb + b_row) * 136 + wn + jp * 16 + b_col;
                uint32_t r[4];
                ldsm4t(r, sBh + ofs);
                bh[2 * jp][0] = r[0]; bh[2 * jp][1] = r[1];
                bh[2 * jp + 1][0] = r[2]; bh[2 * jp + 1][1] = r[3];
                ldsm4t(r, sBl + ofs);
                bl[2 * jp][0] = r[0]; bl[2 * jp][1] = r[1];
                bl[2 * jp + 1][0] = r[2]; bl[2 * jp + 1][1] = r[3];
            }
#pragma unroll
            for (int mt = 0; mt < 2; mt++)
#pragma unroll
                for (int j = 0; j < 8; j++) {
                    mma16816(acc[mt][j], ah[mt], bh[j]);   // hh
                    mma16816(acc[mt][j], ah[mt], bl[j]);   // hl
                    mma16816(acc[mt][j], al[mt], bh[j]);   // lh
                }
        }
        __syncthreads();
    }

    const int g = lane >> 2;
    const int t = lane & 3;
    float* out = g_cv0 + (size_t)b * 8192 * 8192;
#pragma unroll
    for (int mt = 0; mt < 2; mt++) {
        const int mrow = m0 + wm + mt * 16 + g;
#pragma unroll
        for (int j = 0; j < 8; j++) {
            const int n = n0 + wn + j * 8 + 2 * t;
            float2 v0 = make_float2(acc[mt][j][0], acc[mt][j][1]);
            float2 v1 = make_float2(acc[mt][j][2], acc[mt][j][3]);
            *(float2*)&out[(size_t)mrow * 8192 + n] = v0;
            *(float2*)&out[(size_t)(mrow + 8) * 8192 + n] = v1;
        }
    }
}

// ---------------- kernel 2a: ballot-filtered warp-cooperative KNN16 ----------
// One warp per (query, batch, level); top-16 distributed across lanes 0-15.
// Measured 278us isolated (R14). Tie semantics match the serial scan.
__global__ void __launch_bounds__(256) knn16_ballot(const float* __restrict__ xyz1,
                                                    const float* __restrict__ x0,
                                                    const float* __restrict__ x1,
                                                    const float* __restrict__ x2,
                                                    const float* __restrict__ x3)
{
    const int lvl = blockIdx.z;
    const float* pxyz = (lvl == 0) ? x0 : (lvl == 1) ? x1 : (lvl == 2) ? x2 : x3;
    const int Ni      = (lvl == 0) ? 8192 : (lvl == 1) ? 2048 : (lvl == 2) ? 512 : 128;

    __shared__ float4 s4[2048];
    const int b    = blockIdx.y;
    const int warp = threadIdx.x >> 5;
    const int lane = threadIdx.x & 31;
    const int qi   = blockIdx.x * 8 + warp;

    const float qx = xyz1[(size_t)(b * 3 + 0) * N1 + qi];
    const float qy = xyz1[(size_t)(b * 3 + 1) * N1 + qi];
    const float qz = xyz1[(size_t)(b * 3 + 2) * N1 + qi];
    const float qq = qx * qx + qy * qy + qz * qz;

    float myv = 1e30f;
    int   myi = 0;
    float thr = 1e30f;

    for (int c0 = 0; c0 < Ni; c0 += 2048) {
        const int cnt = min(2048, Ni - c0);
        __syncthreads();
        for (int t = threadIdx.x; t < cnt; t += 256) {
            const float ix = pxyz[(size_t)(b * 3 + 0) * Ni + c0 + t];
            const float iy = pxyz[(size_t)(b * 3 + 1) * Ni + c0 + t];
            const float iz = pxyz[(size_t)(b * 3 + 2) * Ni + c0 + t];
            s4[t] = make_float4(ix, iy, iz, ix * ix + iy * iy + iz * iz);
        }
        __syncthreads();

        for (int t = 0; t < cnt; t += 32) {
            const float4 f = s4[t + lane];
            const float d = qq + f.w - 2.0f * (qx * f.x + qy * f.y + qz * f.z);
            unsigned q = __ballot_sync(0xFFFFFFFF, d < thr);
            while (q) {
                const int src = __ffs(q) - 1;
                q &= q - 1;
                const float dd = __shfl_sync(0xFFFFFFFF, d, src);
                if (dd < thr) {
                    const int ii = c0 + t + src;
                    const unsigned m =
                        __ballot_sync(0xFFFFFFFF, (lane < 16) && (myv <= dd));
                    const int p = __popc(m);
                    const float vprev = __shfl_up_sync(0xFFFFFFFF, myv, 1);
                    const int   iprev = __shfl_up_sync(0xFFFFFFFF, myi, 1);
                    if (lane == p)                    { myv = dd;    myi = ii; }
                    else if (lane > p && lane < 16)   { myv = vprev; myi = iprev; }
                    thr = __shfl_sync(0xFFFFFFFF, myv, 15);
                }
            }
        }
    }

    if (lane < 16)
        g_idx[(size_t)lvl * IDX_CROSS_STRIDE + ((size_t)b * N1 + qi) * 16 + lane] = myi;
}

// ---------------- kernel 2c: FUSED warp-per-query KNN3, all 3 levels ---------
__global__ void __launch_bounds__(256) knn3_all(const float* __restrict__ x0,
                                                const float* __restrict__ x1,
                                                const float* __restrict__ x2,
                                                const float* __restrict__ x3)
{
    const int l = blockIdx.z;
    const float* qxyz; const float* pxyz; int Nq, Ni, out_off;
    if (l == 0)      { qxyz = x1; pxyz = x0; Nq = 2048; Ni = 8192; out_off = IDX_PYR1; }
    else if (l == 1) { qxyz = x2; pxyz = x1; Nq = 512;  Ni = 2048; out_off = IDX_PYR2; }
    else             { qxyz = x3; pxyz = x2; Nq = 128;  Ni = 512;  out_off = IDX_PYR3; }
    if (blockIdx.x * 8 >= Nq) return;

    const int CH = 2048;
    __shared__ float sx[CH], sy[CH], sz[CH];
    const int b    = blockIdx.y;
    const int w    = threadIdx.x >> 5;
    const int lane = threadIdx.x & 31;
    const int qi   = blockIdx.x * 8 + w;

    const float qx = qxyz[(size_t)(b * 3 + 0) * Nq + qi];
    const float qy = qxyz[(size_t)(b * 3 + 1) * Nq + qi];
    const float qz = qxyz[(size_t)(b * 3 + 2) * Nq + qi];
    const float qq = qx * qx + qy * qy + qz * qz;

    float bd[3];
    int   bi[3];
#pragma unroll
    for (int j = 0; j < 3; j++) { bd[j] = 1e30f; bi[j] = -(lane + 1); }

    for (int c0 = 0; c0 < Ni; c0 += CH) {
        const int cnt = min(CH, Ni - c0);
        __syncthreads();
        for (int t = threadIdx.x; t < cnt; t += 256) {
            sx[t] = pxyz[(size_t)(b * 3 + 0) * Ni + c0 + t];
            sy[t] = pxyz[(size_t)(b * 3 + 1) * Ni + c0 + t];
            sz[t] = pxyz[(size_t)(b * 3 + 2) * Ni + c0 + t];
        }
        __syncthreads();
        for (int t = lane; t < cnt; t += 32) {
            const float ix = sx[t], iy = sy[t], iz = sz[t];
            const float ii = ix * ix + iy * iy + iz * iz;
            const float d  = qq + ii - 2.0f * (qx * ix + qy * iy + qz * iz);
            if (d < bd[2]) {
                bd[2] = d; bi[2] = c0 + t;
#pragma unroll
                for (int j = 2; j > 0; j--) {
                    if (bd[j] < bd[j - 1]) {
                        float td = bd[j]; bd[j] = bd[j - 1]; bd[j - 1] = td;
                        int   ti = bi[j]; bi[j] = bi[j - 1]; bi[j - 1] = ti;
                    }
                }
            }
        }
    }

    int   p   = 0;
    float myd = bd[0];
    int   myi = bi[0];
    int   res = 0;
#pragma unroll
    for (int j = 0; j < 3; j++) {
        float d = myd; int ii = myi;
#pragma unroll
        for (int off = 16; off; off >>= 1) {
            float od = __shfl_xor_sync(0xFFFFFFFF, d, off);
            int   oi = __shfl_xor_sync(0xFFFFFFFF, ii, off);
            if (od < d || (od == d && oi < ii)) { d = od; ii = oi; }
        }
        if (lane == j) res = ii;
        if (myi == ii) {
            p++;
            if (p < 3) { myd = bd[p]; myi = bi[p]; }
            else       { myd = 1e30f; myi = -(lane + 33); }
        }
    }
    if (lane < 3)
        g_idx[out_off + ((size_t)b * Nq + qi) * 3 + lane] = res;
}

// ---------------- kernel 3: pyramid k=3 average (float4; R10 version) --------
__global__ void __launch_bounds__(256) pyr_avg(int lvl, int Nm, int Nprev, int idx_off)
{
    const float* prev = cv_ptr(lvl - 1);
    float* out        = cv_ptr(lvl);
    const int b = blockIdx.z;
    const int m = blockIdx.y;
    const int n4 = blockIdx.x * 256 + threadIdx.x;
    const int* ip = g_idx + idx_off + ((size_t)b * Nm + m) * 3;
    const int i0 = ip[0], i1 = ip[1], i2 = ip[2];
    const float4 a = *(const float4*)&prev[(((size_t)b * Nprev + i0) * 8192) + n4 * 4];
    const float4 c = *(const float4*)&prev[(((size_t)b * Nprev + i1) * 8192) + n4 * 4];
    const float4 d = *(const float4*)&prev[(((size_t)b * Nprev + i2) * 8192) + n4 * 4];
    float4 v;
    v.x = (a.x + c.x + d.x) * (1.0f / 3.0f);
    v.y = (a.y + c.y + d.y) * (1.0f / 3.0f);
    v.z = (a.z + c.z + d.z) * (1.0f / 3.0f);
    v.w = (a.w + c.w + d.w) * (1.0f / 3.0f);
    *(float4*)&out[(((size_t)b * Nm + m) * 8192) + n4 * 4] = v;
}

// ---------------- kernel 4: FUSED per-level matching cost MLP (R10 version) --
__global__ void __launch_bounds__(128) lc_all(const float* __restrict__ xyz1,
                                              const float* __restrict__ x0,
                                              const float* __restrict__ x1,
                                              const float* __restrict__ x2,
                                              const float* __restrict__ x3,
                                              const float* __restrict__ w1,
                                              const float* __restrict__ b1,
                                              const float* __restrict__ w2,
                                              const float* __restrict__ b2)
{
    __shared__ float sw1[64], sb1[16], sw2[256], sb2[16];
    const int t = threadIdx.x;
    if (t < 64) sw1[t] = w1[t];
    if (t < 16) sb1[t] = b1[t];
    for (int i = t; i < 256; i += 128) sw2[i] = w2[i];
    if (t >= 64 && t < 80) sb2[t - 64] = b2[t - 64];
    __syncthreads();

    const int lvl = blockIdx.z;
    const float* xyz2 = (lvl == 0) ? x0 : (lvl == 1) ? x1 : (lvl == 2) ? x2 : x3;
    const int Nl      = (lvl == 0) ? 8192 : (lvl == 1) ? 2048 : (lvl == 2) ? 512 : 128;

    const int b = blockIdx.y;
    const int n = blockIdx.x * 128 + t;
    const float* cvT = cv_ptr(lvl);
    const int* ip = g_idx + (size_t)lvl * IDX_CROSS_STRIDE + ((size_t)b * N1 + n) * 16;

    const float px = xyz1[(size_t)(b * 3 + 0) * N1 + n];
    const float py = xyz1[(size_t)(b * 3 + 1) * N1 + n];
    const float pz = xyz1[(size_t)(b * 3 + 2) * N1 + n];

    float acc[16];
#pragma unroll
    for (int o = 0; o < 16; o++) acc[o] = 0.0f;

#pragma unroll 4
    for (int k = 0; k < 16; k++) {
        const int i = ip[k];
        const float dx = xyz2[(size_t)(b * 3 + 0) * Nl + i] - px;
        const float dy = xyz2[(size_t)(b * 3 + 1) * Nl + i] - py;
        const float dz = xyz2[(size_t)(b * 3 + 2) * Nl + i] - pz;
        const float corr = cvT[((size_t)b * Nl + i) * 8192 + n];

        float h1[16];
#pragma unroll
        for (int o = 0; o < 16; o++) {
            float a = fmaf(sw1[o * 4 + 0], dx, sb1[o]);
            a = fmaf(sw1[o * 4 + 1], dy, a);
            a = fmaf(sw1[o * 4 + 2], dz, a);
            a = fmaf(sw1[o * 4 + 3], corr, a);
            h1[o] = fmaxf(a, 0.0f);
        }
#pragma unroll
        for (int o2 = 0; o2 < 16; o2++) {
            float a = sb2[o2];
#pragma unroll
            for (int o = 0; o < 16; o++) a = fmaf(sw2[o2 * 16 + o], h1[o], a);
            acc[o2] += fmaxf(a, 0.0f);
        }
    }
#pragma unroll
    for (int o2 = 0; o2 < 16; o2++)
        g_costs[((size_t)b * 64 + lvl * 16 + o2) * N1 + n] = acc[o2];
}

// ---------------- kernel 5: final 64x64 MLP ---------------------------------
__global__ void __launch_bounds__(256) final_mlp(const float* __restrict__ wm,
                                                 const float* __restrict__ bm,
                                                 float* __restrict__ out)
{
    __shared__ float swm[4096];
    __shared__ float sbm[64];
    const int t = threadIdx.x;
    for (int i = t; i < 4096; i += 256) swm[i] = wm[i];
    if (t < 64) sbm[t] = bm[t];
    __syncthreads();

    const int b = blockIdx.y;
    const int n = blockIdx.x * 256 + t;

    float c[64];
#pragma unroll
    for (int cc = 0; cc < 64; cc++)
        c[cc] = g_costs[((size_t)b * 64 + cc) * N1 + n];

#pragma unroll 4
    for (int o = 0; o < 64; o++) {
        float a = sbm[o];
#pragma unroll
        for (int cc = 0; cc < 64; cc++)
            a = fmaf(swm[o * 64 + cc], c[cc], a);
        out[((size_t)b * 64 + o) * N1 + n] = fmaxf(a, 0.0f);
    }
}

// ---------------- launcher ---------------------------------------------------
extern "C" void kernel_launch(void* const* d_in, const int* in_sizes, int n_in,
                              void* d_out, int out_size)
{
    const float* xyz1   = (const float*)d_in[0];
    const float* xyz2_0 = (const float*)d_in[1];
    const float* xyz2_1 = (const float*)d_in[2];
    const float* xyz2_2 = (const float*)d_in[3];
    const float* xyz2_3 = (const float*)d_in[4];
    const float* feat1  = (const float*)d_in[5];
    const float* feat2  = (const float*)d_in[6];
    const float* w1 = (const float*)d_in[7];
    const float* b1 = (const float*)d_in[8];
    const float* w2 = (const float*)d_in[9];
    const float* b2 = (const float*)d_in[10];
    const float* wm = (const float*)d_in[11];
    const float* bm = (const float*)d_in[12];
    float* out = (float*)d_out;

    static bool init = false;
    static cudaStream_t s1, s2;
    static cudaEvent_t ev0, evK3, evK16;
    if (!init) {
        cudaFuncSetAttribute(gemm_cv_mma, cudaFuncAttributeMaxDynamicSharedMemorySize,
                             GEMM_SMEM_BYTES);
        cudaStreamCreateWithFlags(&s1, cudaStreamNonBlocking);
        cudaStreamCreateWithFlags(&s2, cudaStreamNonBlocking);
        cudaEventCreateWithFlags(&ev0,  cudaEventDisableTiming);
        cudaEventCreateWithFlags(&evK3, cudaEventDisableTiming);
        cudaEventCreateWithFlags(&evK16, cudaEventDisableTiming);
        init = true;
    }

    // ---- fork ----
    cudaEventRecord(ev0, 0);
    cudaStreamWaitEvent(s1, ev0, 0);
    cudaStreamWaitEvent(s2, ev0, 0);

    // #1: pyramid KNN (s1)
    knn3_all<<<dim3(256, 2, 3), 256, 0, s1>>>(xyz2_0, xyz2_1, xyz2_2, xyz2_3);
    cudaEventRecord(evK3, s1);

    // #2: bf16 split (default)
    split_bf16<<<FEAT_ELEMS / 256, 256>>>(feat1, feat2);

    // #3: cost volume GEMM level 0 (default)
    gemm_cv_mma<<<dim3(64, 64, 2), 256, GEMM_SMEM_BYTES>>>();

    // #4: pyramid averaging level 1 (default)  <-- profiled launch
    cudaStreamWaitEvent(0, evK3, 0);
    pyr_avg<<<dim3(8, 2048, 2), 256>>>(1, 2048, 8192, IDX_PYR1);
    // #5-6: remaining pyramid levels
    pyr_avg<<<dim3(8,  512, 2), 256>>>(2,  512, 2048, IDX_PYR2);
    pyr_avg<<<dim3(8,  128, 2), 256>>>(3,  128,  512, IDX_PYR3);

    // #7: cross KNN, ballot-filtered (s2) — starts at t=0, overlaps the above
    knn16_ballot<<<dim3(1024, 2, 4), 256, 0, s2>>>(xyz1, xyz2_0, xyz2_1, xyz2_2, xyz2_3);
    cudaEventRecord(evK16, s2);

    // join, then matching cost + final MLP on default stream
    cudaStreamWaitEvent(0, evK16, 0);
    lc_all<<<dim3(64, 2, 4), 128>>>(xyz1, xyz2_0, xyz2_1, xyz2_2, xyz2_3,
                                    w1, b1, w2, b2);
    final_mlp<<<dim3(32, 2), 256>>>(wm, bm, out);
}

// round 16
// speedup vs baseline: 1.9924x; 1.0180x over previous
#include <cuda_runtime.h>
#include <cuda_bf16.h>
#include <cstdint>

#define BATCH 2
#define N1 8192
#define CIN 128

// ---------------- scratch (device globals; no allocations allowed) ----------
static __device__ float g_cv0[134217728];   // [2][8192][8192]  512 MB
static __device__ float g_cv1[33554432];    // [2][2048][8192]  128 MB
static __device__ float g_cv2[8388608];     // [2][ 512][8192]   32 MB
static __device__ float g_cv3[2097152];     // [2][ 128][8192]    8 MB
#define IDX_CROSS_STRIDE 262144            // 2*8192*16
#define IDX_PYR_BASE     1048576
#define IDX_PYR1         (IDX_PYR_BASE)
#define IDX_PYR2         (IDX_PYR_BASE + 12288)
#define IDX_PYR3         (IDX_PYR_BASE + 15360)
static __device__ int   g_idx[1048576 + 16128];
static __device__ float g_costs [1048576];  // [2][64][8192]  (neighbors 0-7)
static __device__ float g_costs2[1048576];  // [2][64][8192]  (neighbors 8-15)

// bf16 split operands, layout [b][k][m]
#define FEAT_ELEMS 2097152                 // 2*128*8192
static __device__ __nv_bfloat16 g_f1h[FEAT_ELEMS];
static __device__ __nv_bfloat16 g_f1l[FEAT_ELEMS];
static __device__ __nv_bfloat16 g_f2h[FEAT_ELEMS];   // scaled by 1/128
static __device__ __nv_bfloat16 g_f2l[FEAT_ELEMS];

__device__ __forceinline__ float* cv_ptr(int lvl) {
    switch (lvl) {
        case 0: return g_cv0;
        case 1: return g_cv1;
        case 2: return g_cv2;
        default: return g_cv3;
    }
}

// ---------------- kernel 0: bf16 hi/lo split ---------------------------------
__global__ void __launch_bounds__(256) split_bf16(const float* __restrict__ feat1,
                                                  const float* __restrict__ feat2)
{
    const int i = blockIdx.x * 256 + threadIdx.x;
    if (i >= FEAT_ELEMS) return;
    {
        float a = feat1[i];
        __nv_bfloat16 h = __float2bfloat16_rn(a);
        g_f1h[i] = h;
        g_f1l[i] = __float2bfloat16_rn(a - __bfloat162float(h));
    }
    {
        float a = feat2[i] * 0.0078125f;   // fold 1/128 (exact pow2)
        __nv_bfloat16 h = __float2bfloat16_rn(a);
        g_f2h[i] = h;
        g_f2l[i] = __float2bfloat16_rn(a - __bfloat162float(h));
    }
}

// ---------------- kernel 1: cost volume GEMM (bf16 split, mma.sync) ----------
#define BK 32
#define STAGE_ELEMS 4352
#define GEMM_SMEM_BYTES (8 * STAGE_ELEMS * 2)

__device__ __forceinline__ void cp_async16(void* smem, const void* gmem) {
    unsigned saddr = (unsigned)__cvta_generic_to_shared(smem);
    asm volatile("cp.async.cg.shared.global [%0], [%1], 16;\n" :: "r"(saddr), "l"(gmem));
}
__device__ __forceinline__ void ldsm4t(uint32_t r[4], const __nv_bfloat16* p) {
    unsigned saddr = (unsigned)__cvta_generic_to_shared((void*)p);
    asm volatile("ldmatrix.sync.aligned.m8n8.x4.trans.shared.b16 {%0,%1,%2,%3}, [%4];"
                 : "=r"(r[0]), "=r"(r[1]), "=r"(r[2]), "=r"(r[3]) : "r"(saddr));
}
__device__ __forceinline__ void mma16816(float d[4], const uint32_t a[4], const uint32_t b[2]) {
    asm volatile("mma.sync.aligned.m16n8k16.row.col.f32.bf16.bf16.f32 "
                 "{%0,%1,%2,%3}, {%4,%5,%6,%7}, {%8,%9}, {%0,%1,%2,%3};"
                 : "+f"(d[0]), "+f"(d[1]), "+f"(d[2]), "+f"(d[3])
                 : "r"(a[0]), "r"(a[1]), "r"(a[2]), "r"(a[3]), "r"(b[0]), "r"(b[1]));
}

__global__ void __launch_bounds__(256) gemm_cv_mma()
{
    extern __shared__ __nv_bfloat16 sm[];
    __nv_bfloat16* sAh = sm;
    __nv_bfloat16* sAl = sm + 2 * STAGE_ELEMS;
    __nv_bfloat16* sBh = sm + 4 * STAGE_ELEMS;
    __nv_bfloat16* sBl = sm + 6 * STAGE_ELEMS;

    const int b  = blockIdx.z;
    const int m0 = blockIdx.y * 128;
    const int n0 = blockIdx.x * 128;
    const int tid  = threadIdx.x;
    const int lane = tid & 31;
    const int warp = tid >> 5;
    const int wm = (warp & 3) * 32;
    const int wn = (warp >> 2) * 64;

    const __nv_bfloat16* gAh = g_f2h + (size_t)b * CIN * 8192 + m0;
    const __nv_bfloat16* gAl = g_f2l + (size_t)b * CIN * 8192 + m0;
    const __nv_bfloat16* gBh = g_f1h + (size_t)b * CIN * 8192 + n0;
    const __nv_bfloat16* gBl = g_f1l + (size_t)b * CIN * 8192 + n0;

    const int l_row0 = tid >> 4;
    const int l_col0 = (tid & 15) * 8;
#define LOAD_STAGE(stg, k0)                                                          \
    {                                                                                \
        _Pragma("unroll")                                                            \
        for (int i = 0; i < 2; i++) {                                                \
            int row = l_row0 + i * 16;                                               \
            size_t gofs = (size_t)((k0) + row) * 8192 + l_col0;                      \
            int sofs = (stg) * STAGE_ELEMS + row * 136 + l_col0;                     \
            cp_async16(sAh + sofs, gAh + gofs);                                      \
            cp_async16(sAl + sofs, gAl + gofs);                                      \
            cp_async16(sBh + sofs, gBh + gofs);                                      \
            cp_async16(sBl + sofs, gBl + gofs);                                      \
        }                                                                            \
        asm volatile("cp.async.commit_group;\n" ::);                                 \
    }

    float acc[2][8][4];
#pragma unroll
    for (int mt = 0; mt < 2; mt++)
#pragma unroll
        for (int j = 0; j < 8; j++)
#pragma unroll
            for (int r = 0; r < 4; r++) acc[mt][j][r] = 0.0f;

    const int a_row = (lane & 7) + ((lane >> 4) << 3);
    const int a_col = ((lane >> 3) & 1) * 8;
    const int b_row = (lane & 7) + (((lane >> 3) & 1) << 3);
    const int b_col = ((lane >> 4) << 3);

    LOAD_STAGE(0, 0)

    const int NCHUNK = CIN / BK;
#pragma unroll
    for (int c = 0; c < NCHUNK; c++) {
        if (c + 1 < NCHUNK) {
            LOAD_STAGE((c + 1) & 1, (c + 1) * BK)
            asm volatile("cp.async.wait_group 1;\n" ::);
        } else {
            asm volatile("cp.async.wait_group 0;\n" ::);
        }
        __syncthreads();

        const int stg = (c & 1) * STAGE_ELEMS;
#pragma unroll
        for (int ks = 0; ks < 2; ks++) {
            const int kb = ks * 16;
            uint32_t ah[2][4], al[2][4];
#pragma unroll
            for (int mt = 0; mt < 2; mt++) {
                int ofs = stg + (kb + a_row) * 136 + wm + mt * 16 + a_col;
                ldsm4t(ah[mt], sAh + ofs);
                ldsm4t(al[mt], sAl + ofs);
            }
            uint32_t bh[8][2], bl[8][2];
#pragma unroll
            for (int jp = 0; jp < 4; jp++) {
                int ofs = stg + (kb + b_row) * 136 + wn + jp * 16 + b_col;
                uint32_t r[4];
                ldsm4t(r, sBh + ofs);
                bh[2 * jp][0] = r[0]; bh[2 * jp][1] = r[1];
                bh[2 * jp + 1][0] = r[2]; bh[2 * jp + 1][1] = r[3];
                ldsm4t(r, sBl + ofs);
                bl[2 * jp][0] = r[0]; bl[2 * jp][1] = r[1];
                bl[2 * jp + 1][0] = r[2]; bl[2 * jp + 1][1] = r[3];
            }
#pragma unroll
            for (int mt = 0; mt < 2; mt++)
#pragma unroll
                for (int j = 0; j < 8; j++) {
                    mma16816(acc[mt][j], ah[mt], bh[j]);   // hh
                    mma16816(acc[mt][j], ah[mt], bl[j]);   // hl
                    mma16816(acc[mt][j], al[mt], bh[j]);   // lh
                }
        }
        __syncthreads();
    }

    const int g = lane >> 2;
    const int t = lane & 3;
    float* out = g_cv0 + (size_t)b * 8192 * 8192;
#pragma unroll
    for (int mt = 0; mt < 2; mt++) {
        const int mrow = m0 + wm + mt * 16 + g;
#pragma unroll
        for (int j = 0; j < 8; j++) {
            const int n = n0 + wn + j * 8 + 2 * t;
            float2 v0 = make_float2(acc[mt][j][0], acc[mt][j][1]);
            float2 v1 = make_float2(acc[mt][j][2], acc[mt][j][3]);
            *(float2*)&out[(size_t)mrow * 8192 + n] = v0;
            *(float2*)&out[(size_t)(mrow + 8) * 8192 + n] = v1;
        }
    }
}

// ---------------- kernel 2a: ballot-filtered warp-cooperative KNN16 ----------
// Dual-candidate scan: 64 candidates per loop iteration (shared overhead).
// Insert path and tie semantics unchanged from R14/R15 (measured correct).
__global__ void __launch_bounds__(256) knn16_ballot(const float* __restrict__ xyz1,
                                                    const float* __restrict__ x0,
                                                    const float* __restrict__ x1,
                                                    const float* __restrict__ x2,
                                                    const float* __restrict__ x3)
{
    const int lvl = blockIdx.z;
    const float* pxyz = (lvl == 0) ? x0 : (lvl == 1) ? x1 : (lvl == 2) ? x2 : x3;
    const int Ni      = (lvl == 0) ? 8192 : (lvl == 1) ? 2048 : (lvl == 2) ? 512 : 128;

    __shared__ float4 s4[2048];
    const int b    = blockIdx.y;
    const int warp = threadIdx.x >> 5;
    const int lane = threadIdx.x & 31;
    const int qi   = blockIdx.x * 8 + warp;

    const float qx = xyz1[(size_t)(b * 3 + 0) * N1 + qi];
    const float qy = xyz1[(size_t)(b * 3 + 1) * N1 + qi];
    const float qz = xyz1[(size_t)(b * 3 + 2) * N1 + qi];
    const float qq = qx * qx + qy * qy + qz * qz;

    float myv = 1e30f;
    int   myi = 0;
    float thr = 1e30f;

#define KNN_INSERT(dval, base_idx)                                                   \
    {                                                                                \
        unsigned q = __ballot_sync(0xFFFFFFFF, (dval) < thr);                        \
        while (q) {                                                                  \
            const int src = __ffs(q) - 1;                                            \
            q &= q - 1;                                                              \
            const float dd = __shfl_sync(0xFFFFFFFF, (dval), src);                   \
            if (dd < thr) {                                                          \
                const int ii = (base_idx) + src;                                     \
                const unsigned m =                                                   \
                    __ballot_sync(0xFFFFFFFF, (lane < 16) && (myv <= dd));           \
                const int p = __popc(m);                                             \
                const float vprev = __shfl_up_sync(0xFFFFFFFF, myv, 1);              \
                const int   iprev = __shfl_up_sync(0xFFFFFFFF, myi, 1);              \
                if (lane == p)                    { myv = dd;    myi = ii; }         \
                else if (lane > p && lane < 16)   { myv = vprev; myi = iprev; }      \
                thr = __shfl_sync(0xFFFFFFFF, myv, 15);                              \
            }                                                                        \
        }                                                                            \
    }

    for (int c0 = 0; c0 < Ni; c0 += 2048) {
        const int cnt = min(2048, Ni - c0);     // multiples of 64 at every level
        __syncthreads();
        for (int t = threadIdx.x; t < cnt; t += 256) {
            const float ix = pxyz[(size_t)(b * 3 + 0) * Ni + c0 + t];
            const float iy = pxyz[(size_t)(b * 3 + 1) * Ni + c0 + t];
            const float iz = pxyz[(size_t)(b * 3 + 2) * Ni + c0 + t];
            s4[t] = make_float4(ix, iy, iz, ix * ix + iy * iy + iz * iz);
        }
        __syncthreads();

        for (int t = 0; t < cnt; t += 64) {
            const float4 f1 = s4[t + lane];
            const float4 f2 = s4[t + 32 + lane];
            const float d1 = qq + f1.w - 2.0f * (qx * f1.x + qy * f1.y + qz * f1.z);
            const float d2 = qq + f2.w - 2.0f * (qx * f2.x + qy * f2.y + qz * f2.z);
            KNN_INSERT(d1, c0 + t)
            KNN_INSERT(d2, c0 + t + 32)
        }
    }

    if (lane < 16)
        g_idx[(size_t)lvl * IDX_CROSS_STRIDE + ((size_t)b * N1 + qi) * 16 + lane] = myi;
}

// ---------------- kernel 2c: FUSED warp-per-query KNN3, all 3 levels ---------
__global__ void __launch_bounds__(256) knn3_all(const float* __restrict__ x0,
                                                const float* __restrict__ x1,
                                                const float* __restrict__ x2,
                                                const float* __restrict__ x3)
{
    const int l = blockIdx.z;
    const float* qxyz; const float* pxyz; int Nq, Ni, out_off;
    if (l == 0)      { qxyz = x1; pxyz = x0; Nq = 2048; Ni = 8192; out_off = IDX_PYR1; }
    else if (l == 1) { qxyz = x2; pxyz = x1; Nq = 512;  Ni = 2048; out_off = IDX_PYR2; }
    else             { qxyz = x3; pxyz = x2; Nq = 128;  Ni = 512;  out_off = IDX_PYR3; }
    if (blockIdx.x * 8 >= Nq) return;

    const int CH = 2048;
    __shared__ float sx[CH], sy[CH], sz[CH];
    const int b    = blockIdx.y;
    const int w    = threadIdx.x >> 5;
    const int lane = threadIdx.x & 31;
    const int qi   = blockIdx.x * 8 + w;

    const float qx = qxyz[(size_t)(b * 3 + 0) * Nq + qi];
    const float qy = qxyz[(size_t)(b * 3 + 1) * Nq + qi];
    const float qz = qxyz[(size_t)(b * 3 + 2) * Nq + qi];
    const float qq = qx * qx + qy * qy + qz * qz;

    float bd[3];
    int   bi[3];
#pragma unroll
    for (int j = 0; j < 3; j++) { bd[j] = 1e30f; bi[j] = -(lane + 1); }

    for (int c0 = 0; c0 < Ni; c0 += CH) {
        const int cnt = min(CH, Ni - c0);
        __syncthreads();
        for (int t = threadIdx.x; t < cnt; t += 256) {
            sx[t] = pxyz[(size_t)(b * 3 + 0) * Ni + c0 + t];
            sy[t] = pxyz[(size_t)(b * 3 + 1) * Ni + c0 + t];
            sz[t] = pxyz[(size_t)(b * 3 + 2) * Ni + c0 + t];
        }
        __syncthreads();
        for (int t = lane; t < cnt; t += 32) {
            const float ix = sx[t], iy = sy[t], iz = sz[t];
            const float ii = ix * ix + iy * iy + iz * iz;
            const float d  = qq + ii - 2.0f * (qx * ix + qy * iy + qz * iz);
            if (d < bd[2]) {
                bd[2] = d; bi[2] = c0 + t;
#pragma unroll
                for (int j = 2; j > 0; j--) {
                    if (bd[j] < bd[j - 1]) {
                        float td = bd[j]; bd[j] = bd[j - 1]; bd[j - 1] = td;
                        int   ti = bi[j]; bi[j] = bi[j - 1]; bi[j - 1] = ti;
                    }
                }
            }
        }
    }

    int   p   = 0;
    float myd = bd[0];
    int   myi = bi[0];
    int   res = 0;
#pragma unroll
    for (int j = 0; j < 3; j++) {
        float d = myd; int ii = myi;
#pragma unroll
        for (int off = 16; off; off >>= 1) {
            float od = __shfl_xor_sync(0xFFFFFFFF, d, off);
            int   oi = __shfl_xor_sync(0xFFFFFFFF, ii, off);
            if (od < d || (od == d && oi < ii)) { d = od; ii = oi; }
        }
        if (lane == j) res = ii;
        if (myi == ii) {
            p++;
            if (p < 3) { myd = bd[p]; myi = bi[p]; }
            else       { myd = 1e30f; myi = -(lane + 33); }
        }
    }
    if (lane < 3)
        g_idx[out_off + ((size_t)b * Nq + qi) * 3 + lane] = res;
}

// ---------------- kernel 3: pyramid k=3 average (float4) ---------------------
__global__ void __launch_bounds__(256) pyr_avg(int lvl, int Nm, int Nprev, int idx_off)
{
    const float* prev = cv_ptr(lvl - 1);
    float* out        = cv_ptr(lvl);
    const int b = blockIdx.z;
    const int m = blockIdx.y;
    const int n4 = blockIdx.x * 256 + threadIdx.x;
    const int* ip = g_idx + idx_off + ((size_t)b * Nm + m) * 3;
    const int i0 = ip[0], i1 = ip[1], i2 = ip[2];
    const float4 a = *(const float4*)&prev[(((size_t)b * Nprev + i0) * 8192) + n4 * 4];
    const float4 c = *(const float4*)&prev[(((size_t)b * Nprev + i1) * 8192) + n4 * 4];
    const float4 d = *(const float4*)&prev[(((size_t)b * Nprev + i2) * 8192) + n4 * 4];
    float4 v;
    v.x = (a.x + c.x + d.x) * (1.0f / 3.0f);
    v.y = (a.y + c.y + d.y) * (1.0f / 3.0f);
    v.z = (a.z + c.z + d.z) * (1.0f / 3.0f);
    v.w = (a.w + c.w + d.w) * (1.0f / 3.0f);
    *(float4*)&out[(((size_t)b * Nm + m) * 8192) + n4 * 4] = v;
}

// ---------------- kernel 4: matching cost MLP, SPLIT-K (2x parallelism) ------
// z = lvl*2 + half; half h handles neighbors h*8..h*8+7, partial sums to
// g_costs (h=0) / g_costs2 (h=1); final_mlp adds them.
__global__ void __launch_bounds__(128) lc_all(const float* __restrict__ xyz1,
                                              const float* __restrict__ x0,
                                              const float* __restrict__ x1,
                                              const float* __restrict__ x2,
                                              const float* __restrict__ x3,
                                              const float* __restrict__ w1,
                                              const float* __restrict__ b1,
                                              const float* __restrict__ w2,
                                              const float* __restrict__ b2)
{
    __shared__ float sw1[64], sb1[16], sw2[256], sb2[16];
    const int t = threadIdx.x;
    if (t < 64) sw1[t] = w1[t];
    if (t < 16) sb1[t] = b1[t];
    for (int i = t; i < 256; i += 128) sw2[i] = w2[i];
    if (t >= 64 && t < 80) sb2[t - 64] = b2[t - 64];
    __syncthreads();

    const int z = blockIdx.z;
    const int lvl = z >> 1, half = z & 1;
    const float* xyz2 = (lvl == 0) ? x0 : (lvl == 1) ? x1 : (lvl == 2) ? x2 : x3;
    const int Nl      = (lvl == 0) ? 8192 : (lvl == 1) ? 2048 : (lvl == 2) ? 512 : 128;

    const int b = blockIdx.y;
    const int n = blockIdx.x * 128 + t;
    const float* cvT = cv_ptr(lvl);
    const int* ip = g_idx + (size_t)lvl * IDX_CROSS_STRIDE
                  + ((size_t)b * N1 + n) * 16 + half * 8;

    const float px = xyz1[(size_t)(b * 3 + 0) * N1 + n];
    const float py = xyz1[(size_t)(b * 3 + 1) * N1 + n];
    const float pz = xyz1[(size_t)(b * 3 + 2) * N1 + n];

    float acc[16];
#pragma unroll
    for (int o = 0; o < 16; o++) acc[o] = 0.0f;

#pragma unroll 4
    for (int k = 0; k < 8; k++) {
        const int i = ip[k];
        const float dx = xyz2[(size_t)(b * 3 + 0) * Nl + i] - px;
        const float dy = xyz2[(size_t)(b * 3 + 1) * Nl + i] - py;
        const float dz = xyz2[(size_t)(b * 3 + 2) * Nl + i] - pz;
        const float corr = cvT[((size_t)b * Nl + i) * 8192 + n];

        float h1[16];
#pragma unroll
        for (int o = 0; o < 16; o++) {
            float a = fmaf(sw1[o * 4 + 0], dx, sb1[o]);
            a = fmaf(sw1[o * 4 + 1], dy, a);
            a = fmaf(sw1[o * 4 + 2], dz, a);
            a = fmaf(sw1[o * 4 + 3], corr, a);
            h1[o] = fmaxf(a, 0.0f);
        }
#pragma unroll
        for (int o2 = 0; o2 < 16; o2++) {
            float a = sb2[o2];
#pragma unroll
            for (int o = 0; o < 16; o++) a = fmaf(sw2[o2 * 16 + o], h1[o], a);
            acc[o2] += fmaxf(a, 0.0f);
        }
    }
    float* dst = half ? g_costs2 : g_costs;
#pragma unroll
    for (int o2 = 0; o2 < 16; o2++)
        dst[((size_t)b * 64 + lvl * 16 + o2) * N1 + n] = acc[o2];
}

// ---------------- kernel 5: final 64x64 MLP (sums the two lc halves) ---------
__global__ void __launch_bounds__(256) final_mlp(const float* __restrict__ wm,
                                                 const float* __restrict__ bm,
                                                 float* __restrict__ out)
{
    __shared__ float swm[4096];
    __shared__ float sbm[64];
    const int t = threadIdx.x;
    for (int i = t; i < 4096; i += 256) swm[i] = wm[i];
    if (t < 64) sbm[t] = bm[t];
    __syncthreads();

    const int b = blockIdx.y;
    const int n = blockIdx.x * 256 + t;

    float c[64];
#pragma unroll
    for (int cc = 0; cc < 64; cc++) {
        const size_t idx = ((size_t)b * 64 + cc) * N1 + n;
        c[cc] = g_costs[idx] + g_costs2[idx];
    }

#pragma unroll 4
    for (int o = 0; o < 64; o++) {
        float a = sbm[o];
#pragma unroll
        for (int cc = 0; cc < 64; cc++)
            a = fmaf(swm[o * 64 + cc], c[cc], a);
        out[((size_t)b * 64 + o) * N1 + n] = fmaxf(a, 0.0f);
    }
}

// ---------------- launcher ---------------------------------------------------
extern "C" void kernel_launch(void* const* d_in, const int* in_sizes, int n_in,
                              void* d_out, int out_size)
{
    const float* xyz1   = (const float*)d_in[0];
    const float* xyz2_0 = (const float*)d_in[1];
    const float* xyz2_1 = (const float*)d_in[2];
    const float* xyz2_2 = (const float*)d_in[3];
    const float* xyz2_3 = (const float*)d_in[4];
    const float* feat1  = (const float*)d_in[5];
    const float* feat2  = (const float*)d_in[6];
    const float* w1 = (const float*)d_in[7];
    const float* b1 = (const float*)d_in[8];
    const float* w2 = (const float*)d_in[9];
    const float* b2 = (const float*)d_in[10];
    const float* wm = (const float*)d_in[11];
    const float* bm = (const float*)d_in[12];
    float* out = (float*)d_out;

    static bool init = false;
    static cudaStream_t s1, s2;
    static cudaEvent_t ev0, evK3, evK16;
    if (!init) {
        cudaFuncSetAttribute(gemm_cv_mma, cudaFuncAttributeMaxDynamicSharedMemorySize,
                             GEMM_SMEM_BYTES);
        cudaStreamCreateWithFlags(&s1, cudaStreamNonBlocking);
        cudaStreamCreateWithFlags(&s2, cudaStreamNonBlocking);
        cudaEventCreateWithFlags(&ev0,  cudaEventDisableTiming);
        cudaEventCreateWithFlags(&evK3, cudaEventDisableTiming);
        cudaEventCreateWithFlags(&evK16, cudaEventDisableTiming);
        init = true;
    }

    // ---- fork ----
    cudaEventRecord(ev0, 0);
    cudaStreamWaitEvent(s1, ev0, 0);
    cudaStreamWaitEvent(s2, ev0, 0);

    // #1: pyramid KNN (s1)
    knn3_all<<<dim3(256, 2, 3), 256, 0, s1>>>(xyz2_0, xyz2_1, xyz2_2, xyz2_3);
    cudaEventRecord(evK3, s1);

    // #2: bf16 split (default)
    split_bf16<<<FEAT_ELEMS / 256, 256>>>(feat1, feat2);

    // #3: cost volume GEMM level 0 (default)
    gemm_cv_mma<<<dim3(64, 64, 2), 256, GEMM_SMEM_BYTES>>>();

    // #4: cross KNN, ballot-filtered dual-scan (s2)  <-- profiled launch
    knn16_ballot<<<dim3(1024, 2, 4), 256, 0, s2>>>(xyz1, xyz2_0, xyz2_1, xyz2_2, xyz2_3);
    cudaEventRecord(evK16, s2);

    // #5-7: pyramid averaging chain (default)
    cudaStreamWaitEvent(0, evK3, 0);
    pyr_avg<<<dim3(8, 2048, 2), 256>>>(1, 2048, 8192, IDX_PYR1);
    pyr_avg<<<dim3(8,  512, 2), 256>>>(2,  512, 2048, IDX_PYR2);
    pyr_avg<<<dim3(8,  128, 2), 256>>>(3,  128,  512, IDX_PYR3);

    // join, then matching cost (split-k) + final MLP on default stream
    cudaStreamWaitEvent(0, evK16, 0);
    lc_all<<<dim3(64, 2, 8), 128>>>(xyz1, xyz2_0, xyz2_1, xyz2_2, xyz2_3,
                                    w1, b1, w2, b2);
    final_mlp<<<dim3(32, 2), 256>>>(wm, bm, out);
}

// round 17
// speedup vs baseline: 2.0444x; 1.0261x over previous
#include <cuda_runtime.h>
#include <cuda_bf16.h>
#include <cstdint>

#define BATCH 2
#define N1 8192
#define CIN 128

// ---------------- scratch (device globals; no allocations allowed) ----------
static __device__ float g_cv0[134217728];   // [2][8192][8192]  512 MB
static __device__ float g_cv1[33554432];    // [2][2048][8192]  128 MB
static __device__ float g_cv2[8388608];     // [2][ 512][8192]   32 MB
static __device__ float g_cv3[2097152];     // [2][ 128][8192]    8 MB
#define IDX_CROSS_STRIDE 262144            // 2*8192*16
#define IDX_PYR_BASE     1048576
#define IDX_PYR1         (IDX_PYR_BASE)
#define IDX_PYR2         (IDX_PYR_BASE + 12288)
#define IDX_PYR3         (IDX_PYR_BASE + 15360)
static __device__ int   g_idx[1048576 + 16128];
static __device__ float g_costs [1048576];  // [2][64][8192]  (neighbors 0-7)
static __device__ float g_costs2[1048576];  // [2][64][8192]  (neighbors 8-15)

// bf16 split operands, layout [b][k][m]
#define FEAT_ELEMS 2097152                 // 2*128*8192
static __device__ __nv_bfloat16 g_f1h[FEAT_ELEMS];
static __device__ __nv_bfloat16 g_f1l[FEAT_ELEMS];
static __device__ __nv_bfloat16 g_f2h[FEAT_ELEMS];   // scaled by 1/128
static __device__ __nv_bfloat16 g_f2l[FEAT_ELEMS];

__device__ __forceinline__ float* cv_ptr(int lvl) {
    switch (lvl) {
        case 0: return g_cv0;
        case 1: return g_cv1;
        case 2: return g_cv2;
        default: return g_cv3;
    }
}

// ---------------- kernel 0: bf16 hi/lo split ---------------------------------
__global__ void __launch_bounds__(256) split_bf16(const float* __restrict__ feat1,
                                                  const float* __restrict__ feat2)
{
    const int i = blockIdx.x * 256 + threadIdx.x;
    if (i >= FEAT_ELEMS) return;
    {
        float a = feat1[i];
        __nv_bfloat16 h = __float2bfloat16_rn(a);
        g_f1h[i] = h;
        g_f1l[i] = __float2bfloat16_rn(a - __bfloat162float(h));
    }
    {
        float a = feat2[i] * 0.0078125f;   // fold 1/128 (exact pow2)
        __nv_bfloat16 h = __float2bfloat16_rn(a);
        g_f2h[i] = h;
        g_f2l[i] = __float2bfloat16_rn(a - __bfloat162float(h));
    }
}

// ---------------- kernel 1: cost volume GEMM (bf16 split, mma.sync) ----------
#define BK 32
#define STAGE_ELEMS 4352
#define GEMM_SMEM_BYTES (8 * STAGE_ELEMS * 2)

__device__ __forceinline__ void cp_async16(void* smem, const void* gmem) {
    unsigned saddr = (unsigned)__cvta_generic_to_shared(smem);
    asm volatile("cp.async.cg.shared.global [%0], [%1], 16;\n" :: "r"(saddr), "l"(gmem));
}
__device__ __forceinline__ void ldsm4t(uint32_t r[4], const __nv_bfloat16* p) {
    unsigned saddr = (unsigned)__cvta_generic_to_shared((void*)p);
    asm volatile("ldmatrix.sync.aligned.m8n8.x4.trans.shared.b16 {%0,%1,%2,%3}, [%4];"
                 : "=r"(r[0]), "=r"(r[1]), "=r"(r[2]), "=r"(r[3]) : "r"(saddr));
}
__device__ __forceinline__ void mma16816(float d[4], const uint32_t a[4], const uint32_t b[2]) {
    asm volatile("mma.sync.aligned.m16n8k16.row.col.f32.bf16.bf16.f32 "
                 "{%0,%1,%2,%3}, {%4,%5,%6,%7}, {%8,%9}, {%0,%1,%2,%3};"
                 : "+f"(d[0]), "+f"(d[1]), "+f"(d[2]), "+f"(d[3])
                 : "r"(a[0]), "r"(a[1]), "r"(a[2]), "r"(a[3]), "r"(b[0]), "r"(b[1]));
}

__global__ void __launch_bounds__(256) gemm_cv_mma()
{
    extern __shared__ __nv_bfloat16 sm[];
    __nv_bfloat16* sAh = sm;
    __nv_bfloat16* sAl = sm + 2 * STAGE_ELEMS;
    __nv_bfloat16* sBh = sm + 4 * STAGE_ELEMS;
    __nv_bfloat16* sBl = sm + 6 * STAGE_ELEMS;

    const int b  = blockIdx.z;
    const int m0 = blockIdx.y * 128;
    const int n0 = blockIdx.x * 128;
    const int tid  = threadIdx.x;
    const int lane = tid & 31;
    const int warp = tid >> 5;
    const int wm = (warp & 3) * 32;
    const int wn = (warp >> 2) * 64;

    const __nv_bfloat16* gAh = g_f2h + (size_t)b * CIN * 8192 + m0;
    const __nv_bfloat16* gAl = g_f2l + (size_t)b * CIN * 8192 + m0;
    const __nv_bfloat16* gBh = g_f1h + (size_t)b * CIN * 8192 + n0;
    const __nv_bfloat16* gBl = g_f1l + (size_t)b * CIN * 8192 + n0;

    const int l_row0 = tid >> 4;
    const int l_col0 = (tid & 15) * 8;
#define LOAD_STAGE(stg, k0)                                                          \
    {                                                                                \
        _Pragma("unroll")                                                            \
        for (int i = 0; i < 2; i++) {                                                \
            int row = l_row0 + i * 16;                                               \
            size_t gofs = (size_t)((k0) + row) * 8192 + l_col0;                      \
            int sofs = (stg) * STAGE_ELEMS + row * 136 + l_col0;                     \
            cp_async16(sAh + sofs, gAh + gofs);                                      \
            cp_async16(sAl + sofs, gAl + gofs);                                      \
            cp_async16(sBh + sofs, gBh + gofs);                                      \
            cp_async16(sBl + sofs, gBl + gofs);                                      \
        }                                                                            \
        asm volatile("cp.async.commit_group;\n" ::);                                 \
    }

    float acc[2][8][4];
#pragma unroll
    for (int mt = 0; mt < 2; mt++)
#pragma unroll
        for (int j = 0; j < 8; j++)
#pragma unroll
            for (int r = 0; r < 4; r++) acc[mt][j][r] = 0.0f;

    const int a_row = (lane & 7) + ((lane >> 4) << 3);
    const int a_col = ((lane >> 3) & 1) * 8;
    const int b_row = (lane & 7) + (((lane >> 3) & 1) << 3);
    const int b_col = ((lane >> 4) << 3);

    LOAD_STAGE(0, 0)

    const int NCHUNK = CIN / BK;
#pragma unroll
    for (int c = 0; c < NCHUNK; c++) {
        if (c + 1 < NCHUNK) {
            LOAD_STAGE((c + 1) & 1, (c + 1) * BK)
            asm volatile("cp.async.wait_group 1;\n" ::);
        } else {
            asm volatile("cp.async.wait_group 0;\n" ::);
        }
        __syncthreads();

        const int stg = (c & 1) * STAGE_ELEMS;
#pragma unroll
        for (int ks = 0; ks < 2; ks++) {
            const int kb = ks * 16;
            uint32_t ah[2][4], al[2][4];
#pragma unroll
            for (int mt = 0; mt < 2; mt++) {
                int ofs = stg + (kb + a_row) * 136 + wm + mt * 16 + a_col;
                ldsm4t(ah[mt], sAh + ofs);
                ldsm4t(al[mt], sAl + ofs);
            }
            uint32_t bh[8][2], bl[8][2];
#pragma unroll
            for (int jp = 0; jp < 4; jp++) {
                int ofs = stg + (kb + b_row) * 136 + wn + jp * 16 + b_col;
                uint32_t r[4];
                ldsm4t(r, sBh + ofs);
                bh[2 * jp][0] = r[0]; bh[2 * jp][1] = r[1];
                bh[2 * jp + 1][0] = r[2]; bh[2 * jp + 1][1] = r[3];
                ldsm4t(r, sBl + ofs);
                bl[2 * jp][0] = r[0]; bl[2 * jp][1] = r[1];
                bl[2 * jp + 1][0] = r[2]; bl[2 * jp + 1][1] = r[3];
            }
#pragma unroll
            for (int mt = 0; mt < 2; mt++)
#pragma unroll
                for (int j = 0; j < 8; j++) {
                    mma16816(acc[mt][j], ah[mt], bh[j]);   // hh
                    mma16816(acc[mt][j], ah[mt], bl[j]);   // hl
                    mma16816(acc[mt][j], al[mt], bh[j]);   // lh
                }
        }
        __syncthreads();
    }

    const int g = lane >> 2;
    const int t = lane & 3;
    float* out = g_cv0 + (size_t)b * 8192 * 8192;
#pragma unroll
    for (int mt = 0; mt < 2; mt++) {
        const int mrow = m0 + wm + mt * 16 + g;
#pragma unroll
        for (int j = 0; j < 8; j++) {
            const int n = n0 + wn + j * 8 + 2 * t;
            float2 v0 = make_float2(acc[mt][j][0], acc[mt][j][1]);
            float2 v1 = make_float2(acc[mt][j][2], acc[mt][j][3]);
            *(float2*)&out[(size_t)mrow * 8192 + n] = v0;
            *(float2*)&out[(size_t)(mrow + 8) * 8192 + n] = v1;
        }
    }
}

// ---------------- kernel 2a: ballot KNN16, TWO queries per warp --------------
// Lanes 0-15 hold query A's sorted top-16; lanes 16-31 hold query B's.
// Each candidate LDS.128 now feeds BOTH queries' distance evals (halves the
// smem-crossbar traffic that dominated R16's 263us). Insert paths mirror the
// proven single-query version; tie semantics identical to the serial scan.
__global__ void __launch_bounds__(256) knn16_ballot(const float* __restrict__ xyz1,
                                                    const float* __restrict__ x0,
                                                    const float* __restrict__ x1,
                                                    const float* __restrict__ x2,
                                                    const float* __restrict__ x3)
{
    const int lvl = blockIdx.z;
    const float* pxyz = (lvl == 0) ? x0 : (lvl == 1) ? x1 : (lvl == 2) ? x2 : x3;
    const int Ni      = (lvl == 0) ? 8192 : (lvl == 1) ? 2048 : (lvl == 2) ? 512 : 128;

    __shared__ float4 s4[2048];
    const int b    = blockIdx.y;
    const int warp = threadIdx.x >> 5;
    const int lane = threadIdx.x & 31;
    const int qA   = blockIdx.x * 16 + warp * 2;
    const int qB   = qA + 1;

    const float qxA = xyz1[(size_t)(b * 3 + 0) * N1 + qA];
    const float qyA = xyz1[(size_t)(b * 3 + 1) * N1 + qA];
    const float qzA = xyz1[(size_t)(b * 3 + 2) * N1 + qA];
    const float qqA = qxA * qxA + qyA * qyA + qzA * qzA;
    const float qxB = xyz1[(size_t)(b * 3 + 0) * N1 + qB];
    const float qyB = xyz1[(size_t)(b * 3 + 1) * N1 + qB];
    const float qzB = xyz1[(size_t)(b * 3 + 2) * N1 + qB];
    const float qqB = qxB * qxB + qyB * qyB + qzB * qzB;

    float myv = 1e30f;
    int   myi = 0;
    float thrA = 1e30f, thrB = 1e30f;

#define INS_A(dval, base_idx)                                                        \
    {                                                                                \
        unsigned q = __ballot_sync(0xFFFFFFFF, (dval) < thrA);                       \
        while (q) {                                                                  \
            const int src = __ffs(q) - 1;                                            \
            q &= q - 1;                                                              \
            const float dd = __shfl_sync(0xFFFFFFFF, (dval), src);                   \
            if (dd < thrA) {                                                         \
                const int ii = (base_idx) + src;                                     \
                const unsigned m =                                                   \
                    __ballot_sync(0xFFFFFFFF, (lane < 16) && (myv <= dd));           \
                const int p = __popc(m);                                             \
                const float vprev = __shfl_up_sync(0xFFFFFFFF, myv, 1);              \
                const int   iprev = __shfl_up_sync(0xFFFFFFFF, myi, 1);              \
                if (lane == p)                    { myv = dd;    myi = ii; }         \
                else if (lane > p && lane < 16)   { myv = vprev; myi = iprev; }      \
                thrA = __shfl_sync(0xFFFFFFFF, myv, 15);                             \
            }                                                                        \
        }                                                                            \
    }
#define INS_B(dval, base_idx)                                                        \
    {                                                                                \
        unsigned q = __ballot_sync(0xFFFFFFFF, (dval) < thrB);                       \
        while (q) {                                                                  \
            const int src = __ffs(q) - 1;                                            \
            q &= q - 1;                                                              \
            const float dd = __shfl_sync(0xFFFFFFFF, (dval), src);                   \
            if (dd < thrB) {                                                         \
                const int ii = (base_idx) + src;                                     \
                const unsigned m =                                                   \
                    __ballot_sync(0xFFFFFFFF, (lane >= 16) && (myv <= dd));          \
                const int p = 16 + __popc(m);                                        \
                const float vprev = __shfl_up_sync(0xFFFFFFFF, myv, 1);              \
                const int   iprev = __shfl_up_sync(0xFFFFFFFF, myi, 1);              \
                if (lane == p)        { myv = dd;    myi = ii; }                     \
                else if (lane > p)    { myv = vprev; myi = iprev; }                  \
                thrB = __shfl_sync(0xFFFFFFFF, myv, 31);                             \
            }                                                                        \
        }                                                                            \
    }

    for (int c0 = 0; c0 < Ni; c0 += 2048) {
        const int cnt = min(2048, Ni - c0);     // multiples of 64 at every level
        __syncthreads();
        for (int t = threadIdx.x; t < cnt; t += 256) {
            const float ix = pxyz[(size_t)(b * 3 + 0) * Ni + c0 + t];
            const float iy = pxyz[(size_t)(b * 3 + 1) * Ni + c0 + t];
            const float iz = pxyz[(size_t)(b * 3 + 2) * Ni + c0 + t];
            s4[t] = make_float4(ix, iy, iz, ix * ix + iy * iy + iz * iz);
        }
        __syncthreads();

        for (int t = 0; t < cnt; t += 64) {
            const float4 f1 = s4[t + lane];
            const float4 f2 = s4[t + 32 + lane];
            const float dA1 = qqA + f1.w - 2.0f * (qxA * f1.x + qyA * f1.y + qzA * f1.z);
            const float dA2 = qqA + f2.w - 2.0f * (qxA * f2.x + qyA * f2.y + qzA * f2.z);
            const float dB1 = qqB + f1.w - 2.0f * (qxB * f1.x + qyB * f1.y + qzB * f1.z);
            const float dB2 = qqB + f2.w - 2.0f * (qxB * f2.x + qyB * f2.y + qzB * f2.z);
            INS_A(dA1, c0 + t)
            INS_A(dA2, c0 + t + 32)
            INS_B(dB1, c0 + t)
            INS_B(dB2, c0 + t + 32)
        }
    }

    if (lane < 16)
        g_idx[(size_t)lvl * IDX_CROSS_STRIDE + ((size_t)b * N1 + qA) * 16 + lane] = myi;
    else
        g_idx[(size_t)lvl * IDX_CROSS_STRIDE + ((size_t)b * N1 + qB) * 16 + (lane - 16)] = myi;
}

// ---------------- kernel 2c: FUSED warp-per-query KNN3, all 3 levels ---------
__global__ void __launch_bounds__(256) knn3_all(const float* __restrict__ x0,
                                                const float* __restrict__ x1,
                                                const float* __restrict__ x2,
                                                const float* __restrict__ x3)
{
    const int l = blockIdx.z;
    const float* qxyz; const float* pxyz; int Nq, Ni, out_off;
    if (l == 0)      { qxyz = x1; pxyz = x0; Nq = 2048; Ni = 8192; out_off = IDX_PYR1; }
    else if (l == 1) { qxyz = x2; pxyz = x1; Nq = 512;  Ni = 2048; out_off = IDX_PYR2; }
    else             { qxyz = x3; pxyz = x2; Nq = 128;  Ni = 512;  out_off = IDX_PYR3; }
    if (blockIdx.x * 8 >= Nq) return;

    const int CH = 2048;
    __shared__ float sx[CH], sy[CH], sz[CH];
    const int b    = blockIdx.y;
    const int w    = threadIdx.x >> 5;
    const int lane = threadIdx.x & 31;
    const int qi   = blockIdx.x * 8 + w;

    const float qx = qxyz[(size_t)(b * 3 + 0) * Nq + qi];
    const float qy = qxyz[(size_t)(b * 3 + 1) * Nq + qi];
    const float qz = qxyz[(size_t)(b * 3 + 2) * Nq + qi];
    const float qq = qx * qx + qy * qy + qz * qz;

    float bd[3];
    int   bi[3];
#pragma unroll
    for (int j = 0; j < 3; j++) { bd[j] = 1e30f; bi[j] = -(lane + 1); }

    for (int c0 = 0; c0 < Ni; c0 += CH) {
        const int cnt = min(CH, Ni - c0);
        __syncthreads();
        for (int t = threadIdx.x; t < cnt; t += 256) {
            sx[t] = pxyz[(size_t)(b * 3 + 0) * Ni + c0 + t];
            sy[t] = pxyz[(size_t)(b * 3 + 1) * Ni + c0 + t];
            sz[t] = pxyz[(size_t)(b * 3 + 2) * Ni + c0 + t];
        }
        __syncthreads();
        for (int t = lane; t < cnt; t += 32) {
            const float ix = sx[t], iy = sy[t], iz = sz[t];
            const float ii = ix * ix + iy * iy + iz * iz;
            const float d  = qq + ii - 2.0f * (qx * ix + qy * iy + qz * iz);
            if (d < bd[2]) {
                bd[2] = d; bi[2] = c0 + t;
#pragma unroll
                for (int j = 2; j > 0; j--) {
                    if (bd[j] < bd[j - 1]) {
                        float td = bd[j]; bd[j] = bd[j - 1]; bd[j - 1] = td;
                        int   ti = bi[j]; bi[j] = bi[j - 1]; bi[j - 1] = ti;
                    }
                }
            }
        }
    }

    int   p   = 0;
    float myd = bd[0];
    int   myi = bi[0];
    int   res = 0;
#pragma unroll
    for (int j = 0; j < 3; j++) {
        float d = myd; int ii = myi;
#pragma unroll
        for (int off = 16; off; off >>= 1) {
            float od = __shfl_xor_sync(0xFFFFFFFF, d, off);
            int   oi = __shfl_xor_sync(0xFFFFFFFF, ii, off);
            if (od < d || (od == d && oi < ii)) { d = od; ii = oi; }
        }
        if (lane == j) res = ii;
        if (myi == ii) {
            p++;
            if (p < 3) { myd = bd[p]; myi = bi[p]; }
            else       { myd = 1e30f; myi = -(lane + 33); }
        }
    }
    if (lane < 3)
        g_idx[out_off + ((size_t)b * Nq + qi) * 3 + lane] = res;
}

// ---------------- kernel 3: pyramid k=3 average (float4) ---------------------
__global__ void __launch_bounds__(256) pyr_avg(int lvl, int Nm, int Nprev, int idx_off)
{
    const float* prev = cv_ptr(lvl - 1);
    float* out        = cv_ptr(lvl);
    const int b = blockIdx.z;
    const int m = blockIdx.y;
    const int n4 = blockIdx.x * 256 + threadIdx.x;
    const int* ip = g_idx + idx_off + ((size_t)b * Nm + m) * 3;
    const int i0 = ip[0], i1 = ip[1], i2 = ip[2];
    const float4 a = *(const float4*)&prev[(((size_t)b * Nprev + i0) * 8192) + n4 * 4];
    const float4 c = *(const float4*)&prev[(((size_t)b * Nprev + i1) * 8192) + n4 * 4];
    const float4 d = *(const float4*)&prev[(((size_t)b * Nprev + i2) * 8192) + n4 * 4];
    float4 v;
    v.x = (a.x + c.x + d.x) * (1.0f / 3.0f);
    v.y = (a.y + c.y + d.y) * (1.0f / 3.0f);
    v.z = (a.z + c.z + d.z) * (1.0f / 3.0f);
    v.w = (a.w + c.w + d.w) * (1.0f / 3.0f);
    *(float4*)&out[(((size_t)b * Nm + m) * 8192) + n4 * 4] = v;
}

// ---------------- kernel 4: matching cost MLP, SPLIT-K -----------------------
__global__ void __launch_bounds__(128) lc_all(const float* __restrict__ xyz1,
                                              const float* __restrict__ x0,
                                              const float* __restrict__ x1,
                                              const float* __restrict__ x2,
                                              const float* __restrict__ x3,
                                              const float* __restrict__ w1,
                                              const float* __restrict__ b1,
                                              const float* __restrict__ w2,
                                              const float* __restrict__ b2)
{
    __shared__ float sw1[64], sb1[16], sw2[256], sb2[16];
    const int t = threadIdx.x;
    if (t < 64) sw1[t] = w1[t];
    if (t < 16) sb1[t] = b1[t];
    for (int i = t; i < 256; i += 128) sw2[i] = w2[i];
    if (t >= 64 && t < 80) sb2[t - 64] = b2[t - 64];
    __syncthreads();

    const int z = blockIdx.z;
    const int lvl = z >> 1, half = z & 1;
    const float* xyz2 = (lvl == 0) ? x0 : (lvl == 1) ? x1 : (lvl == 2) ? x2 : x3;
    const int Nl      = (lvl == 0) ? 8192 : (lvl == 1) ? 2048 : (lvl == 2) ? 512 : 128;

    const int b = blockIdx.y;
    const int n = blockIdx.x * 128 + t;
    const float* cvT = cv_ptr(lvl);
    const int* ip = g_idx + (size_t)lvl * IDX_CROSS_STRIDE
                  + ((size_t)b * N1 + n) * 16 + half * 8;

    const float px = xyz1[(size_t)(b * 3 + 0) * N1 + n];
    const float py = xyz1[(size_t)(b * 3 + 1) * N1 + n];
    const float pz = xyz1[(size_t)(b * 3 + 2) * N1 + n];

    float acc[16];
#pragma unroll
    for (int o = 0; o < 16; o++) acc[o] = 0.0f;

#pragma unroll 4
    for (int k = 0; k < 8; k++) {
        const int i = ip[k];
        const float dx = xyz2[(size_t)(b * 3 + 0) * Nl + i] - px;
        const float dy = xyz2[(size_t)(b * 3 + 1) * Nl + i] - py;
        const float dz = xyz2[(size_t)(b * 3 + 2) * Nl + i] - pz;
        const float corr = cvT[((size_t)b * Nl + i) * 8192 + n];

        float h1[16];
#pragma unroll
        for (int o = 0; o < 16; o++) {
            float a = fmaf(sw1[o * 4 + 0], dx, sb1[o]);
            a = fmaf(sw1[o * 4 + 1], dy, a);
            a = fmaf(sw1[o * 4 + 2], dz, a);
            a = fmaf(sw1[o * 4 + 3], corr, a);
            h1[o] = fmaxf(a, 0.0f);
        }
#pragma unroll
        for (int o2 = 0; o2 < 16; o2++) {
            float a = sb2[o2];
#pragma unroll
            for (int o = 0; o < 16; o++) a = fmaf(sw2[o2 * 16 + o], h1[o], a);
            acc[o2] += fmaxf(a, 0.0f);
        }
    }
    float* dst = half ? g_costs2 : g_costs;
#pragma unroll
    for (int o2 = 0; o2 < 16; o2++)
        dst[((size_t)b * 64 + lvl * 16 + o2) * N1 + n] = acc[o2];
}

// ---------------- kernel 5: final 64x64 MLP (sums the two lc halves) ---------
__global__ void __launch_bounds__(256) final_mlp(const float* __restrict__ wm,
                                                 const float* __restrict__ bm,
                                                 float* __restrict__ out)
{
    __shared__ float swm[4096];
    __shared__ float sbm[64];
    const int t = threadIdx.x;
    for (int i = t; i < 4096; i += 256) swm[i] = wm[i];
    if (t < 64) sbm[t] = bm[t];
    __syncthreads();

    const int b = blockIdx.y;
    const int n = blockIdx.x * 256 + t;

    float c[64];
#pragma unroll
    for (int cc = 0; cc < 64; cc++) {
        const size_t idx = ((size_t)b * 64 + cc) * N1 + n;
        c[cc] = g_costs[idx] + g_costs2[idx];
    }

#pragma unroll 4
    for (int o = 0; o < 64; o++) {
        float a = sbm[o];
#pragma unroll
        for (int cc = 0; cc < 64; cc++)
            a = fmaf(swm[o * 64 + cc], c[cc], a);
        out[((size_t)b * 64 + o) * N1 + n] = fmaxf(a, 0.0f);
    }
}

// ---------------- launcher ---------------------------------------------------
extern "C" void kernel_launch(void* const* d_in, const int* in_sizes, int n_in,
                              void* d_out, int out_size)
{
    const float* xyz1   = (const float*)d_in[0];
    const float* xyz2_0 = (const float*)d_in[1];
    const float* xyz2_1 = (const float*)d_in[2];
    const float* xyz2_2 = (const float*)d_in[3];
    const float* xyz2_3 = (const float*)d_in[4];
    const float* feat1  = (const float*)d_in[5];
    const float* feat2  = (const float*)d_in[6];
    const float* w1 = (const float*)d_in[7];
    const float* b1 = (const float*)d_in[8];
    const float* w2 = (const float*)d_in[9];
    const float* b2 = (const float*)d_in[10];
    const float* wm = (const float*)d_in[11];
    const float* bm = (const float*)d_in[12];
    float* out = (float*)d_out;

    static bool init = false;
    static cudaStream_t s1, s2;
    static cudaEvent_t ev0, evK3, evK16;
    if (!init) {
        cudaFuncSetAttribute(gemm_cv_mma, cudaFuncAttributeMaxDynamicSharedMemorySize,
                             GEMM_SMEM_BYTES);
        cudaStreamCreateWithFlags(&s1, cudaStreamNonBlocking);
        cudaStreamCreateWithFlags(&s2, cudaStreamNonBlocking);
        cudaEventCreateWithFlags(&ev0,  cudaEventDisableTiming);
        cudaEventCreateWithFlags(&evK3, cudaEventDisableTiming);
        cudaEventCreateWithFlags(&evK16, cudaEventDisableTiming);
        init = true;
    }

    // ---- fork ----
    cudaEventRecord(ev0, 0);
    cudaStreamWaitEvent(s1, ev0, 0);
    cudaStreamWaitEvent(s2, ev0, 0);

    // #1: pyramid KNN (s1)
    knn3_all<<<dim3(256, 2, 3), 256, 0, s1>>>(xyz2_0, xyz2_1, xyz2_2, xyz2_3);
    cudaEventRecord(evK3, s1);

    // #2: bf16 split (default)
    split_bf16<<<FEAT_ELEMS / 256, 256>>>(feat1, feat2);

    // #3: cost volume GEMM level 0 (default)
    gemm_cv_mma<<<dim3(64, 64, 2), 256, GEMM_SMEM_BYTES>>>();

    // #4: cross KNN, 2-queries-per-warp ballot (s2)  <-- profiled launch
    knn16_ballot<<<dim3(512, 2, 4), 256, 0, s2>>>(xyz1, xyz2_0, xyz2_1, xyz2_2, xyz2_3);
    cudaEventRecord(evK16, s2);

    // #5-7: pyramid averaging chain (default)
    cudaStreamWaitEvent(0, evK3, 0);
    pyr_avg<<<dim3(8, 2048, 2), 256>>>(1, 2048, 8192, IDX_PYR1);
    pyr_avg<<<dim3(8,  512, 2), 256>>>(2,  512, 2048, IDX_PYR2);
    pyr_avg<<<dim3(8,  128, 2), 256>>>(3,  128,  512, IDX_PYR3);

    // join, then matching cost (split-k) + final MLP on default stream
    cudaStreamWaitEvent(0, evK16, 0);
    lc_all<<<dim3(64, 2, 8), 128>>>(xyz1, xyz2_0, xyz2_1, xyz2_2, xyz2_3,
                                    w1, b1, w2, b2);
    final_mlp<<<dim3(32, 2), 256>>>(wm, bm, out);
}